// round 13
// baseline (speedup 1.0000x reference)
#include <cuda_runtime.h>
#include <cuda_fp16.h>
#include <cstdint>

// Problem constants
#define PB   2
#define PN   150000
#define PC   64
#define PD   128
#define PD3  (PD*PD*PD)
#define BN   (PB*PN)
#define TOTE (BN*PC)
#define EPSV 1e-4f
#define STAT_BLOCKS 1024

#define TILE_M 256
#define NTILES ((PN + TILE_M - 1) / TILE_M)   // 586

// scan config (Morton ranking)
#define SCAN_CELLS 2048
#define SCAN_BPB   (PD3 / SCAN_CELLS)         // 1024 blocks per batch

// smem layout (bytes) for sparse conv kernel  (EXACTLY R5/R11/R12)
#define ACC_STRIDE 66
#define OFF_ACC   0
#define OFF_A     67584
#define OFF_W     86016
#define OFF_LIST  104448
#define OFF_WCNT  104960
#define SMEM_SP   105216

// ---------------- device scratch ----------------
__device__ int    g_lut[PB * PD3];                  // orig-space hash grid
__device__ int    g_mort[PB * PD3];                 // morton scatter (n+1, 0=empty)
__device__ int    g_bsum[PB * SCAN_BPB];
__device__ int    g_o2s[BN];                        // sorted_of_orig (per-batch local)
__device__ int    g_s2o[BN];                        // orig_of_sorted (per-batch local)
__device__ int    g_nbr[27 * BN];                   // sorted-space neighbors
__device__ __half g_tmp16[(size_t)BN * PC];
__device__ __half g_h16[(size_t)BN * PC];
__device__ float  g_xs[(size_t)BN * PC];            // sorted-space f32 activations
__device__ __half g_wt16[4 * 27 * PC * PC];
__device__ float  g_part[2 * STAT_BLOCKS * PC];
__device__ float  g_scale[PC];
__device__ float  g_shift[PC];

// ---------------- helpers ----------------
__device__ __forceinline__ uint32_t smem_u32(const void* p) {
    uint32_t a;
    asm("{ .reg .u64 t; cvta.to.shared.u64 t, %1; cvt.u32.u64 %0, t; }" : "=r"(a) : "l"(p));
    return a;
}
__device__ __forceinline__ uint32_t part3(uint32_t v) {   // spread 7 bits -> every 3rd
    v = (v | (v << 8)) & 0x0300F00Fu;
    v = (v | (v << 4)) & 0x030C30C3u;
    v = (v | (v << 2)) & 0x09249249u;
    return v;
}

// ---------------- prep ----------------
__global__ void prep0_kernel(const float* __restrict__ Ws) {
    int i = blockIdx.x * blockDim.x + threadIdx.x;
    if (i < PB * PD3) { g_lut[i] = -1; g_mort[i] = 0; }
    if (i < 4 * 27 * 4096) {
        int mat = i >> 12;
        int co  = (i >> 6) & 63;
        int ci  = i & 63;
        g_wt16[i] = __float2half_rn(Ws[mat * 4096 + ci * 64 + co]);
    }
}
__global__ void scatter_kernel(const int* __restrict__ pos) {
    int i = blockIdx.x * blockDim.x + threadIdx.x;
    if (i >= BN) return;
    int b = i / PN, n = i - b * PN;
    int px = pos[3 * i], py = pos[3 * i + 1], pz = pos[3 * i + 2];
    g_lut[b * PD3 + ((px * PD + py) * PD + pz)] = n;
    uint32_t m = (part3(px) << 2) | (part3(py) << 1) | part3(pz);
    g_mort[b * PD3 + m] = n + 1;
}
// scan pass A: per-block occupancy counts
__global__ void scanA_kernel() {
    __shared__ int sred[256];
    int t = threadIdx.x;
    int base = blockIdx.x * SCAN_CELLS + t * 8;
    int cnt = 0;
#pragma unroll
    for (int j = 0; j < 8; j++) cnt += (g_mort[base + j] != 0);
    sred[t] = cnt;
    __syncthreads();
    for (int s = 128; s > 0; s >>= 1) {
        if (t < s) sred[t] += sred[t + s];
        __syncthreads();
    }
    if (t == 0) g_bsum[blockIdx.x] = sred[0];
}
// scan pass B: exclusive prefix of block sums (per batch)
__global__ void scanB_kernel() {
    __shared__ int sc[SCAN_BPB];
    int t = threadIdx.x;                  // 1024
    int b = blockIdx.x;
    int own = g_bsum[b * SCAN_BPB + t];
    sc[t] = own;
    __syncthreads();
    for (int off = 1; off < SCAN_BPB; off <<= 1) {
        int u = (t >= off) ? sc[t - off] : 0;
        __syncthreads();
        sc[t] += u;
        __syncthreads();
    }
    g_bsum[b * SCAN_BPB + t] = sc[t] - own;   // exclusive
}
// scan pass C: assign ranks, build both permutations
__global__ void scanC_kernel() {
    __shared__ int sc[256];
    int t = threadIdx.x;
    int base = blockIdx.x * SCAN_CELLS + t * 8;
    int b = blockIdx.x >> 10;            // 1024 blocks per batch
    int flags[8];
    int cnt = 0;
#pragma unroll
    for (int j = 0; j < 8; j++) { flags[j] = g_mort[base + j]; cnt += (flags[j] != 0); }
    int own = cnt;
    sc[t] = cnt;
    __syncthreads();
    for (int off = 1; off < 256; off <<= 1) {
        int u = (t >= off) ? sc[t - off] : 0;
        __syncthreads();
        sc[t] += u;
        __syncthreads();
    }
    int r = g_bsum[blockIdx.x] + sc[t] - own;
#pragma unroll
    for (int j = 0; j < 8; j++) {
        if (flags[j]) {
            int n = flags[j] - 1;
            g_s2o[b * PN + r] = n;
            g_o2s[b * PN + n] = r;
            r++;
        }
    }
}
// sorted-space neighbor table
__global__ void build_nbr_kernel(const int* __restrict__ pos) {
    int i = blockIdx.x * blockDim.x + threadIdx.x;
    if (i >= BN) return;
    int b = i / PN;
    int o = g_s2o[i];
    const int* pp = pos + 3 * ((size_t)b * PN + o);
    int px = pp[0], py = pp[1], pz = pp[2];
    const int* lutb = g_lut + b * PD3;
    const int* s2b  = g_o2s + b * PN;
#pragma unroll
    for (int k = 0; k < 27; k++) {
        int nx = px + k / 9 - 1, ny = py + (k / 3) % 3 - 1, nz = pz + k % 3 - 1;
        int ns = -1;
        if (((unsigned)nx < PD) & ((unsigned)ny < PD) & ((unsigned)nz < PD)) {
            int no = lutb[(nx * PD + ny) * PD + nz];
            if (no >= 0) ns = s2b[no];
        }
        g_nbr[k * BN + i] = ns;
    }
}
// permute feats (orig) -> xs (sorted)
__global__ void permute_in_kernel(const float* __restrict__ feats, float* __restrict__ xs) {
    int idx = blockIdx.x * blockDim.x + threadIdx.x;
    if (idx >= BN * 16) return;
    int row = idx >> 4, c4 = idx & 15;
    int b = row / PN;
    int o = g_s2o[row];
    ((float4*)xs)[(size_t)row * 16 + c4] =
        ((const float4*)feats)[((size_t)b * PN + o) * 16 + c4];
}
// permute xs (sorted) -> out (orig)
__global__ void permute_out_kernel(const float* __restrict__ xs, float* __restrict__ out) {
    int idx = blockIdx.x * blockDim.x + threadIdx.x;
    if (idx >= BN * 16) return;
    int row = idx >> 4, c4 = idx & 15;
    int b = row / PN;
    int o = g_s2o[row];
    ((float4*)out)[((size_t)b * PN + o) * 16 + c4] =
        ((const float4*)xs)[(size_t)row * 16 + c4];
}

// ---------------- BN: f32 input (R12) ----------------
__global__ void stats_kernel(const float* __restrict__ x) {
    __shared__ float red[2048];
    int t = threadIdx.x;
    size_t gid = (size_t)blockIdx.x * 256 + t;
    const float4* x4 = (const float4*)x;
    float4 s = make_float4(0, 0, 0, 0), q = make_float4(0, 0, 0, 0);
    for (size_t i = gid; i < (size_t)TOTE / 4; i += (size_t)256 * STAT_BLOCKS) {
        float4 v = x4[i];
        s.x += v.x; s.y += v.y; s.z += v.z; s.w += v.w;
        q.x += v.x * v.x; q.y += v.y * v.y; q.z += v.z * v.z; q.w += v.w * v.w;
    }
    red[t * 4 + 0] = s.x; red[t * 4 + 1] = s.y; red[t * 4 + 2] = s.z; red[t * 4 + 3] = s.w;
    red[1024 + t * 4 + 0] = q.x; red[1024 + t * 4 + 1] = q.y;
    red[1024 + t * 4 + 2] = q.z; red[1024 + t * 4 + 3] = q.w;
    __syncthreads();
    if (t < 64) {
        int comp = t & 3, grp = t >> 2;
        float S = 0.f, Q = 0.f;
#pragma unroll
        for (int m = 0; m < 16; m++) {
            int o = grp + m * 16;
            S += red[o * 4 + comp];
            Q += red[1024 + o * 4 + comp];
        }
        g_part[blockIdx.x * 64 + t] = S;
        g_part[STAT_BLOCKS * 64 + blockIdx.x * 64 + t] = Q;
    }
}

// ---------------- BN: fp16 input (R12) ----------------
__global__ void stats16_kernel(const __half* __restrict__ x) {
    __shared__ float red[4096];
    int t = threadIdx.x;
    size_t gid = (size_t)blockIdx.x * 256 + t;
    const uint4* x8 = (const uint4*)x;
    float s[8] = {0, 0, 0, 0, 0, 0, 0, 0}, q[8] = {0, 0, 0, 0, 0, 0, 0, 0};
    for (size_t i = gid; i < (size_t)TOTE / 8; i += (size_t)256 * STAT_BLOCKS) {
        uint4 u = x8[i];
        const __half2* h2 = (const __half2*)&u;
#pragma unroll
        for (int j = 0; j < 4; j++) {
            float2 f = __half22float2(h2[j]);
            s[2 * j] += f.x;     q[2 * j] += f.x * f.x;
            s[2 * j + 1] += f.y; q[2 * j + 1] += f.y * f.y;
        }
    }
#pragma unroll
    for (int j = 0; j < 8; j++) { red[t * 8 + j] = s[j]; red[2048 + t * 8 + j] = q[j]; }
    __syncthreads();
    if (t < 64) {
        int grp = t >> 3;
        int sub = t & 7;
        float S = 0.f, Q = 0.f;
#pragma unroll
        for (int m = 0; m < 32; m++) {
            int tt = grp + m * 8;
            S += red[tt * 8 + sub];
            Q += red[2048 + tt * 8 + sub];
        }
        g_part[blockIdx.x * 64 + t] = S;
        g_part[STAT_BLOCKS * 64 + blockIdx.x * 64 + t] = Q;
    }
}

__global__ void finalize_stats_kernel(const float* __restrict__ gamma,
                                      const float* __restrict__ beta) {
    __shared__ float r[512];
    int t = threadIdx.x;
    int c = t & 63, seg = t >> 6;
    float S = 0.f, Q = 0.f;
    for (int b = seg * 256; b < (seg + 1) * 256; b++) {
        S += g_part[b * 64 + c];
        Q += g_part[STAT_BLOCKS * 64 + b * 64 + c];
    }
    r[t] = S; r[256 + t] = Q;
    __syncthreads();
    if (t < 64) {
        float s = r[t] + r[t + 64] + r[t + 128] + r[t + 192];
        float q = r[256 + t] + r[256 + t + 64] + r[256 + t + 128] + r[256 + t + 192];
        const float inv = 1.0f / (float)BN;
        float mu = s * inv;
        float var = q * inv - mu * mu;
        float rstd = rsqrtf(var + EPSV);
        float sc = rstd * gamma[t];
        g_scale[t] = sc;
        g_shift[t] = beta[t] - mu * sc;
    }
}

__global__ void bnrelu_kernel(const float* __restrict__ x, __half* __restrict__ y) {
    int i = blockIdx.x * blockDim.x + threadIdx.x;
    if (i >= TOTE / 8) return;
    const float4* x4 = (const float4*)x;
    float4 v0 = x4[2 * i], v1 = x4[2 * i + 1];
    int c8 = i & 7;
    float4 sc0 = ((const float4*)g_scale)[2 * c8], sc1 = ((const float4*)g_scale)[2 * c8 + 1];
    float4 sh0 = ((const float4*)g_shift)[2 * c8], sh1 = ((const float4*)g_shift)[2 * c8 + 1];
    __half2 h[4];
    h[0] = __floats2half2_rn(fmaxf(fmaf(v0.x, sc0.x, sh0.x), 0.f),
                             fmaxf(fmaf(v0.y, sc0.y, sh0.y), 0.f));
    h[1] = __floats2half2_rn(fmaxf(fmaf(v0.z, sc0.z, sh0.z), 0.f),
                             fmaxf(fmaf(v0.w, sc0.w, sh0.w), 0.f));
    h[2] = __floats2half2_rn(fmaxf(fmaf(v1.x, sc1.x, sh1.x), 0.f),
                             fmaxf(fmaf(v1.y, sc1.y, sh1.y), 0.f));
    h[3] = __floats2half2_rn(fmaxf(fmaf(v1.z, sc1.z, sh1.z), 0.f),
                             fmaxf(fmaf(v1.w, sc1.w, sh1.w), 0.f));
    ((uint4*)y)[i] = *(uint4*)h;
}

__global__ void bnrelu16_kernel(const __half* __restrict__ x, __half* __restrict__ y) {
    int i = blockIdx.x * blockDim.x + threadIdx.x;
    if (i >= TOTE / 8) return;
    uint4 u = ((const uint4*)x)[i];
    const __half2* h2 = (const __half2*)&u;
    int c8 = i & 7;
    float4 sc0 = ((const float4*)g_scale)[2 * c8], sc1 = ((const float4*)g_scale)[2 * c8 + 1];
    float4 sh0 = ((const float4*)g_shift)[2 * c8], sh1 = ((const float4*)g_shift)[2 * c8 + 1];
    float2 f0 = __half22float2(h2[0]), f1 = __half22float2(h2[1]);
    float2 f2 = __half22float2(h2[2]), f3 = __half22float2(h2[3]);
    __half2 h[4];
    h[0] = __floats2half2_rn(fmaxf(fmaf(f0.x, sc0.x, sh0.x), 0.f),
                             fmaxf(fmaf(f0.y, sc0.y, sh0.y), 0.f));
    h[1] = __floats2half2_rn(fmaxf(fmaf(f1.x, sc0.z, sh0.z), 0.f),
                             fmaxf(fmaf(f1.y, sc0.w, sh0.w), 0.f));
    h[2] = __floats2half2_rn(fmaxf(fmaf(f2.x, sc1.x, sh1.x), 0.f),
                             fmaxf(fmaf(f2.y, sc1.y, sh1.y), 0.f));
    h[3] = __floats2half2_rn(fmaxf(fmaf(f3.x, sc1.z, sh1.z), 0.f),
                             fmaxf(fmaf(f3.y, sc1.w, sh1.w), 0.f));
    ((uint4*)y)[i] = *(uint4*)h;
}

// ---------------- sparse conv (EXACTLY R12) ----------------
template <typename OutT>
__global__ __launch_bounds__(256, 2) void conv_sp_kernel(
    const __half* __restrict__ h, const __half* __restrict__ wt,
    OutT* __restrict__ out, const float* __restrict__ addsrc) {
    extern __shared__ char smem[];
    const uint32_t sbase = smem_u32(smem);
    const int tid  = threadIdx.x;
    const int lane = tid & 31;
    const int wid  = tid >> 5;
    const int g    = lane >> 2;
    const int tig  = lane & 3;
    const int b    = blockIdx.y;
    const int pt0  = blockIdx.x * TILE_M;
    const __half* hb = h + (size_t)b * PN * PC;

    float* accf  = (float*)smem;
    int*   slist = (int*)(smem + OFF_LIST);
    int*   swcnt = (int*)(smem + OFF_WCNT);

    {
        float2 z = make_float2(0.f, 0.f);
        float2* a2 = (float2*)smem;
#pragma unroll
        for (int i = 0; i < 33; i++) a2[tid + 256 * i] = z;
    }

    const int  gp   = pt0 + tid;
    const bool inr  = gp < PN;
    const size_t gidx = (size_t)b * PN + gp;

    int pref = inr ? g_nbr[gidx] : -1;
    int nidx = -1, rank = 0, cnt = 0;

    auto new_tap = [&](int k) {
        nidx = pref;
        pref = (k + 1 < 27 && inr) ? g_nbr[(size_t)(k + 1) * BN + gidx] : -1;
        unsigned msk = __ballot_sync(0xffffffffu, nidx >= 0);
        if (lane == 0) swcnt[wid] = __popc(msk);
        __syncthreads();
        int base = 0, tot = 0;
#pragma unroll
        for (int j = 0; j < 8; j++) {
            int c = swcnt[j];
            base += (j < wid) ? c : 0;
            tot += c;
        }
        rank = base + __popc(msk & ((1u << lane) - 1u));
        cnt = tot;
        __syncthreads();
    };

    auto issue_w = [&](int k, int ws) {
        const char* src = (const char*)(wt + (size_t)k * 4096);
#pragma unroll
        for (int j = 0; j < 2; j++) {
            int c = tid + j * 256;
            int row = c >> 3, off = (c & 7) * 16;
            uint32_t dst = sbase + OFF_W + ws * 9216 + row * 144 + off;
            asm volatile("cp.async.ca.shared.global [%0],[%1],16;"
                         :: "r"(dst), "l"(src + row * 128 + off));
        }
    };

    auto fill_list = [&](int lo, int st) {
        if (nidx >= 0 && rank >= lo && rank < lo + 64)
            slist[st * 64 + (rank - lo)] = (nidx << 8) | tid;
    };

    auto issue_a = [&](int Rc, int st) {
        int row = tid >> 2, q = tid & 3;
        if (row < Rc) {
            int e = slist[st * 64 + row];
            const char* src = (const char*)(hb + ((size_t)(e >> 8)) * PC) + q * 32;
            uint32_t dst = sbase + OFF_A + st * 9216 + row * 144 + q * 32;
            asm volatile("cp.async.ca.shared.global [%0],[%1],16;" :: "r"(dst), "l"(src));
            asm volatile("cp.async.ca.shared.global [%0],[%1],16;" :: "r"(dst + 16), "l"(src + 16));
        }
        asm volatile("cp.async.commit_group;" ::: "memory");
    };

    uint32_t bw[4][2];
    auto load_b = [&](int ws) {
#pragma unroll
        for (int j = 0; j < 4; j++) {
            uint32_t ad = sbase + OFF_W + ws * 9216 +
                          (uint32_t)(wid * 8 + (lane & 7)) * 144 + j * 32 +
                          ((lane >> 3) & 1) * 16;
            asm volatile("ldmatrix.sync.aligned.m8n8.x2.shared.b16 {%0,%1},[%2];"
                         : "=r"(bw[j][0]), "=r"(bw[j][1]) : "r"(ad));
        }
    };

    auto do_chunk = [&](int st, int Rc) {
        int Mc = (Rc + 15) >> 4;
        uint32_t ab = sbase + OFF_A + st * 9216 + (uint32_t)(lane & 15) * 144 +
                      (lane >> 4) * 16;
        for (int mt = 0; mt < Mc; mt++) {
            uint32_t a[4];
            float c[4] = {0.f, 0.f, 0.f, 0.f};
#pragma unroll
            for (int j = 0; j < 4; j++) {
                asm volatile("ldmatrix.sync.aligned.m8n8.x4.shared.b16 {%0,%1,%2,%3},[%4];"
                             : "=r"(a[0]), "=r"(a[1]), "=r"(a[2]), "=r"(a[3])
                             : "r"(ab + mt * 2304 + j * 32));
                asm volatile(
                    "mma.sync.aligned.m16n8k16.row.col.f32.f16.f16.f32 "
                    "{%0,%1,%2,%3},{%4,%5,%6,%7},{%8,%9},{%0,%1,%2,%3};"
                    : "+f"(c[0]), "+f"(c[1]), "+f"(c[2]), "+f"(c[3])
                    : "r"(a[0]), "r"(a[1]), "r"(a[2]), "r"(a[3]),
                      "r"(bw[j][0]), "r"(bw[j][1]));
            }
            int r0 = mt * 16 + g;
            if (r0 < Rc) {
                int t = slist[st * 64 + r0] & 255;
                float2* p = (float2*)(accf + (size_t)t * ACC_STRIDE + wid * 8 + 2 * tig);
                float2 v = *p; v.x += c[0]; v.y += c[1]; *p = v;
            }
            if (r0 + 8 < Rc) {
                int t = slist[st * 64 + r0 + 8] & 255;
                float2* p = (float2*)(accf + (size_t)t * ACC_STRIDE + wid * 8 + 2 * tig);
                float2 v = *p; v.x += c[2]; v.y += c[3]; *p = v;
            }
        }
    };

    int k = 0;
    new_tap(0);
    while (cnt == 0 && k < 26) { k++; new_tap(k); }
    issue_w(k, 0);
    fill_list(0, 0);
    __syncthreads();
    int firstRc = (cnt < 64) ? cnt : 64;
    issue_a(firstRc, 0);

    int curk = k, curlo = 0, curst = 0, curWst = 0, curRc = firstRc;
    bool curNew = true;
    int tapcnt = cnt;

    while (true) {
        int nRc = 0, nst = curst ^ 1, nWst = curWst, nk = curk, nlo = 0;
        bool nNew = false;
        if (curlo + 64 < tapcnt) {
            nk = curk; nlo = curlo + 64;
            nRc = tapcnt - nlo; if (nRc > 64) nRc = 64;
            fill_list(nlo, nst);
            __syncthreads();
            issue_a(nRc, nst);
        } else {
            int k2 = curk + 1;
            while (k2 < 27) { new_tap(k2); if (cnt > 0) break; k2++; }
            if (k2 < 27) {
                nk = k2; nlo = 0; nNew = true; nWst = curWst ^ 1;
                nRc = (cnt < 64) ? cnt : 64;
                issue_w(k2, nWst);
                fill_list(0, nst);
                __syncthreads();
                issue_a(nRc, nst);
            }
        }
        if (nRc > 0) asm volatile("cp.async.wait_group 1;" ::: "memory");
        else         asm volatile("cp.async.wait_group 0;" ::: "memory");
        __syncthreads();
        if (curNew) load_b(curWst);
        do_chunk(curst, curRc);
        __syncthreads();
        if (nRc == 0) break;
        curk = nk; curlo = nlo; curst = nst; curWst = nWst; curNew = nNew; curRc = nRc;
        if (nNew) tapcnt = cnt;
    }

    const bool doadd = (addsrc != nullptr);
    for (int r32 = 0; r32 < 32; r32++) {
        int row = wid * 32 + r32;
        int p = pt0 + row;
        if (p < PN) {
            float2 v = *(float2*)(accf + (size_t)row * ACC_STRIDE + lane * 2);
            size_t o = ((size_t)b * PN + p) * PC + lane * 2;
            if constexpr (sizeof(OutT) == 4) {
                if (doadd) {
                    float2 a2 = *(const float2*)(addsrc + o);
                    v.x += a2.x; v.y += a2.y;
                }
                *(float2*)((float*)out + o) = v;
            } else {
                *(__half2*)((__half*)out + o) = __floats2half2_rn(v.x, v.y);
            }
        }
    }
}

// ---------------- host orchestration ----------------
extern "C" void kernel_launch(void* const* d_in, const int* in_sizes, int n_in,
                              void* d_out, int out_size) {
    const float* feats  = (const float*)d_in[0];
    const float* Ws     = (const float*)d_in[1];
    const float* gammas = (const float*)d_in[2];
    const float* betas  = (const float*)d_in[3];
    const int*   pos    = (const int*)d_in[4];
    float* x = (float*)d_out;

    __half *h16, *wt16, *tmp16;
    float* xs;
    cudaGetSymbolAddress((void**)&h16, g_h16);
    cudaGetSymbolAddress((void**)&wt16, g_wt16);
    cudaGetSymbolAddress((void**)&tmp16, g_tmp16);
    cudaGetSymbolAddress((void**)&xs, g_xs);

    cudaFuncSetAttribute(conv_sp_kernel<float>,
                         cudaFuncAttributeMaxDynamicSharedMemorySize, SMEM_SP);
    cudaFuncSetAttribute(conv_sp_kernel<__half>,
                         cudaFuncAttributeMaxDynamicSharedMemorySize, SMEM_SP);

    // ---- prep: lut + morton rank (deterministic scan) + sorted nbr + permute in
    prep0_kernel<<<(PB * PD3 + 1023) / 1024, 1024>>>(Ws);
    scatter_kernel<<<(BN + 255) / 256, 256>>>(pos);
    scanA_kernel<<<PB * SCAN_BPB, 256>>>();
    scanB_kernel<<<PB, SCAN_BPB>>>();
    scanC_kernel<<<PB * SCAN_BPB, 256>>>();
    build_nbr_kernel<<<(BN + 255) / 256, 256>>>(pos);
    permute_in_kernel<<<(BN * 16 + 255) / 256, 256>>>(feats, xs);

    dim3 cgrid(NTILES, PB);
    const int bnb = (TOTE / 8 + 255) / 256;

    // block 0 (sorted space; residual in-place on xs)
    stats_kernel<<<STAT_BLOCKS, 256>>>(xs);
    finalize_stats_kernel<<<1, 256>>>(gammas + 0 * PC, betas + 0 * PC);
    bnrelu_kernel<<<bnb, 256>>>(xs, h16);
    conv_sp_kernel<__half><<<cgrid, 256, SMEM_SP>>>(
        h16, wt16 + (size_t)0 * 27 * 4096, tmp16, nullptr);
    stats16_kernel<<<STAT_BLOCKS, 256>>>(tmp16);
    finalize_stats_kernel<<<1, 256>>>(gammas + 1 * PC, betas + 1 * PC);
    bnrelu16_kernel<<<bnb, 256>>>(tmp16, h16);
    conv_sp_kernel<float><<<cgrid, 256, SMEM_SP>>>(
        h16, wt16 + (size_t)1 * 27 * 4096, xs, xs);

    // block 1
    stats_kernel<<<STAT_BLOCKS, 256>>>(xs);
    finalize_stats_kernel<<<1, 256>>>(gammas + 2 * PC, betas + 2 * PC);
    bnrelu_kernel<<<bnb, 256>>>(xs, h16);
    conv_sp_kernel<__half><<<cgrid, 256, SMEM_SP>>>(
        h16, wt16 + (size_t)2 * 27 * 4096, tmp16, nullptr);
    stats16_kernel<<<STAT_BLOCKS, 256>>>(tmp16);
    finalize_stats_kernel<<<1, 256>>>(gammas + 3 * PC, betas + 3 * PC);
    bnrelu16_kernel<<<bnb, 256>>>(tmp16, h16);
    conv_sp_kernel<float><<<cgrid, 256, SMEM_SP>>>(
        h16, wt16 + (size_t)3 * 27 * 4096, xs, xs);

    // back to original point order
    permute_out_kernel<<<(BN * 16 + 255) / 256, 256>>>(xs, x);
}

// round 14
// speedup vs baseline: 1.0589x; 1.0589x over previous
#include <cuda_runtime.h>
#include <cuda_fp16.h>
#include <cstdint>

// Problem constants
#define PB   2
#define PN   150000
#define PC   64
#define PD   128
#define PD3  (PD*PD*PD)
#define BN   (PB*PN)
#define TOTE (BN*PC)
#define EPSV 1e-4f
#define STAT_BLOCKS 1024

#define TILE_M 256
#define NTILES ((PN + TILE_M - 1) / TILE_M)   // 586

// smem layout (bytes) for sparse conv kernel  (EXACTLY R5/R11/R12)
#define ACC_STRIDE 66
#define OFF_ACC   0
#define OFF_A     67584
#define OFF_W     86016
#define OFF_LIST  104448
#define OFF_WCNT  104960
#define SMEM_SP   105216

// ---------------- device scratch ----------------
__device__ int      g_lut[PB * PD3];
__device__ int      g_nbr[27 * BN];
__device__ __half   g_tmp16[(size_t)BN * PC];       // conv1/3 output (fp16)
__device__ __half   g_h16[(size_t)BN * PC];         // bn_relu output (fp16 conv input)
__device__ __half   g_wt16[4 * 27 * PC * PC];       // W^T fp16 [conv*27][cout][cin]
__device__ float    g_part[2 * STAT_BLOCKS * PC];
__device__ float    g_scale[PC];
__device__ float    g_shift[PC];
__device__ unsigned g_tick;                         // last-block ticket (self-resetting)

// ---------------- helpers ----------------
__device__ __forceinline__ uint32_t smem_u32(const void* p) {
    uint32_t a;
    asm("{ .reg .u64 t; cvta.to.shared.u64 t, %1; cvt.u32.u64 %0, t; }" : "=r"(a) : "l"(p));
    return a;
}

// shared finalize: reduce all STAT_BLOCKS partials -> scale/shift (fixed order)
__device__ __forceinline__ void finalize_in_block(
    float* red, int t, const float* __restrict__ gamma, const float* __restrict__ beta) {
    int c = t & 63, seg = t >> 6;
    float S = 0.f, Q = 0.f;
    for (int b = seg * 256; b < (seg + 1) * 256; b++) {
        S += g_part[b * 64 + c];
        Q += g_part[STAT_BLOCKS * 64 + b * 64 + c];
    }
    red[t] = S; red[256 + t] = Q;
    __syncthreads();
    if (t < 64) {
        float s = red[t] + red[t + 64] + red[t + 128] + red[t + 192];
        float q = red[256 + t] + red[256 + t + 64] + red[256 + t + 128] + red[256 + t + 192];
        const float inv = 1.0f / (float)BN;
        float mu = s * inv;
        float var = q * inv - mu * mu;
        float rstd = rsqrtf(var + EPSV);
        float sc = rstd * gamma[t];
        g_scale[t] = sc;
        g_shift[t] = beta[t] - mu * sc;
    }
}

// ---------------- prep kernels (R12) ----------------
__global__ void prep0_kernel(const float* __restrict__ Ws) {
    int i = blockIdx.x * blockDim.x + threadIdx.x;
    if (i < PB * PD3) g_lut[i] = -1;
    if (i < 4 * 27 * 4096) {
        int mat = i >> 12;
        int co  = (i >> 6) & 63;
        int ci  = i & 63;
        g_wt16[i] = __float2half_rn(Ws[mat * 4096 + ci * 64 + co]);
    }
}
__global__ void scatter_lut_kernel(const int* __restrict__ pos) {
    int i = blockIdx.x * blockDim.x + threadIdx.x;
    if (i >= BN) return;
    int b = i / PN;
    int code = (pos[3 * i] * PD + pos[3 * i + 1]) * PD + pos[3 * i + 2];
    g_lut[b * PD3 + code] = i - b * PN;
}
__global__ void build_nbr_kernel(const int* __restrict__ pos) {
    int i = blockIdx.x * blockDim.x + threadIdx.x;
    if (i >= BN) return;
    int b = i / PN;
    int px = pos[3 * i], py = pos[3 * i + 1], pz = pos[3 * i + 2];
    const int* lutb = g_lut + b * PD3;
#pragma unroll
    for (int k = 0; k < 27; k++) {
        int nx = px + k / 9 - 1, ny = py + (k / 3) % 3 - 1, nz = pz + k % 3 - 1;
        int nidx = -1;
        if (((unsigned)nx < PD) & ((unsigned)ny < PD) & ((unsigned)nz < PD))
            nidx = lutb[(nx * PD + ny) * PD + nz];
        g_nbr[k * BN + i] = nidx;
    }
}

// ---------------- BN: f32 input, fused finalize ----------------
__global__ void stats_kernel(const float* __restrict__ x,
                             const float* __restrict__ gamma,
                             const float* __restrict__ beta) {
    __shared__ float red[2048];
    __shared__ int is_last;
    int t = threadIdx.x;
    size_t gid = (size_t)blockIdx.x * 256 + t;
    const float4* x4 = (const float4*)x;
    float4 s = make_float4(0, 0, 0, 0), q = make_float4(0, 0, 0, 0);
    for (size_t i = gid; i < (size_t)TOTE / 4; i += (size_t)256 * STAT_BLOCKS) {
        float4 v = x4[i];
        s.x += v.x; s.y += v.y; s.z += v.z; s.w += v.w;
        q.x += v.x * v.x; q.y += v.y * v.y; q.z += v.z * v.z; q.w += v.w * v.w;
    }
    red[t * 4 + 0] = s.x; red[t * 4 + 1] = s.y; red[t * 4 + 2] = s.z; red[t * 4 + 3] = s.w;
    red[1024 + t * 4 + 0] = q.x; red[1024 + t * 4 + 1] = q.y;
    red[1024 + t * 4 + 2] = q.z; red[1024 + t * 4 + 3] = q.w;
    __syncthreads();
    if (t < 64) {
        int comp = t & 3, grp = t >> 2;
        float S = 0.f, Q = 0.f;
#pragma unroll
        for (int m = 0; m < 16; m++) {
            int o = grp + m * 16;
            S += red[o * 4 + comp];
            Q += red[1024 + o * 4 + comp];
        }
        g_part[blockIdx.x * 64 + t] = S;
        g_part[STAT_BLOCKS * 64 + blockIdx.x * 64 + t] = Q;
    }
    __syncthreads();
    if (t == 0) {
        __threadfence();
        unsigned old = atomicAdd(&g_tick, 1u);
        is_last = (old == STAT_BLOCKS - 1);
        if (is_last) g_tick = 0;
    }
    __syncthreads();
    if (is_last) finalize_in_block(red, t, gamma, beta);
}

// ---------------- BN: fp16 input, fused finalize ----------------
__global__ void stats16_kernel(const __half* __restrict__ x,
                               const float* __restrict__ gamma,
                               const float* __restrict__ beta) {
    __shared__ float red[4096];
    __shared__ int is_last;
    int t = threadIdx.x;
    size_t gid = (size_t)blockIdx.x * 256 + t;
    const uint4* x8 = (const uint4*)x;
    float s[8] = {0, 0, 0, 0, 0, 0, 0, 0}, q[8] = {0, 0, 0, 0, 0, 0, 0, 0};
    for (size_t i = gid; i < (size_t)TOTE / 8; i += (size_t)256 * STAT_BLOCKS) {
        uint4 u = x8[i];
        const __half2* h2 = (const __half2*)&u;
#pragma unroll
        for (int j = 0; j < 4; j++) {
            float2 f = __half22float2(h2[j]);
            s[2 * j] += f.x;     q[2 * j] += f.x * f.x;
            s[2 * j + 1] += f.y; q[2 * j + 1] += f.y * f.y;
        }
    }
#pragma unroll
    for (int j = 0; j < 8; j++) { red[t * 8 + j] = s[j]; red[2048 + t * 8 + j] = q[j]; }
    __syncthreads();
    if (t < 64) {
        int grp = t >> 3;
        int sub = t & 7;
        float S = 0.f, Q = 0.f;
#pragma unroll
        for (int m = 0; m < 32; m++) {
            int tt = grp + m * 8;
            S += red[tt * 8 + sub];
            Q += red[2048 + tt * 8 + sub];
        }
        g_part[blockIdx.x * 64 + t] = S;
        g_part[STAT_BLOCKS * 64 + blockIdx.x * 64 + t] = Q;
    }
    __syncthreads();
    if (t == 0) {
        __threadfence();
        unsigned old = atomicAdd(&g_tick, 1u);
        is_last = (old == STAT_BLOCKS - 1);
        if (is_last) g_tick = 0;
    }
    __syncthreads();
    if (is_last) finalize_in_block(red, t, gamma, beta);
}

__global__ void bnrelu_kernel(const float* __restrict__ x, __half* __restrict__ y) {
    int i = blockIdx.x * blockDim.x + threadIdx.x;
    if (i >= TOTE / 8) return;
    const float4* x4 = (const float4*)x;
    float4 v0 = x4[2 * i], v1 = x4[2 * i + 1];
    int c8 = i & 7;
    float4 sc0 = ((const float4*)g_scale)[2 * c8], sc1 = ((const float4*)g_scale)[2 * c8 + 1];
    float4 sh0 = ((const float4*)g_shift)[2 * c8], sh1 = ((const float4*)g_shift)[2 * c8 + 1];
    __half2 h[4];
    h[0] = __floats2half2_rn(fmaxf(fmaf(v0.x, sc0.x, sh0.x), 0.f),
                             fmaxf(fmaf(v0.y, sc0.y, sh0.y), 0.f));
    h[1] = __floats2half2_rn(fmaxf(fmaf(v0.z, sc0.z, sh0.z), 0.f),
                             fmaxf(fmaf(v0.w, sc0.w, sh0.w), 0.f));
    h[2] = __floats2half2_rn(fmaxf(fmaf(v1.x, sc1.x, sh1.x), 0.f),
                             fmaxf(fmaf(v1.y, sc1.y, sh1.y), 0.f));
    h[3] = __floats2half2_rn(fmaxf(fmaf(v1.z, sc1.z, sh1.z), 0.f),
                             fmaxf(fmaf(v1.w, sc1.w, sh1.w), 0.f));
    ((uint4*)y)[i] = *(uint4*)h;
}

__global__ void bnrelu16_kernel(const __half* __restrict__ x, __half* __restrict__ y) {
    int i = blockIdx.x * blockDim.x + threadIdx.x;
    if (i >= TOTE / 8) return;
    uint4 u = ((const uint4*)x)[i];
    const __half2* h2 = (const __half2*)&u;
    int c8 = i & 7;
    float4 sc0 = ((const float4*)g_scale)[2 * c8], sc1 = ((const float4*)g_scale)[2 * c8 + 1];
    float4 sh0 = ((const float4*)g_shift)[2 * c8], sh1 = ((const float4*)g_shift)[2 * c8 + 1];
    float2 f0 = __half22float2(h2[0]), f1 = __half22float2(h2[1]);
    float2 f2 = __half22float2(h2[2]), f3 = __half22float2(h2[3]);
    __half2 h[4];
    h[0] = __floats2half2_rn(fmaxf(fmaf(f0.x, sc0.x, sh0.x), 0.f),
                             fmaxf(fmaf(f0.y, sc0.y, sh0.y), 0.f));
    h[1] = __floats2half2_rn(fmaxf(fmaf(f1.x, sc0.z, sh0.z), 0.f),
                             fmaxf(fmaf(f1.y, sc0.w, sh0.w), 0.f));
    h[2] = __floats2half2_rn(fmaxf(fmaf(f2.x, sc1.x, sh1.x), 0.f),
                             fmaxf(fmaf(f2.y, sc1.y, sh1.y), 0.f));
    h[3] = __floats2half2_rn(fmaxf(fmaf(f3.x, sc1.z, sh1.z), 0.f),
                             fmaxf(fmaf(f3.y, sc1.w, sh1.w), 0.f));
    ((uint4*)y)[i] = *(uint4*)h;
}

// ---------------- sparse conv (EXACTLY R12) ----------------
template <typename OutT>
__global__ __launch_bounds__(256, 2) void conv_sp_kernel(
    const __half* __restrict__ h, const __half* __restrict__ wt,
    OutT* __restrict__ out, const float* __restrict__ addsrc) {
    extern __shared__ char smem[];
    const uint32_t sbase = smem_u32(smem);
    const int tid  = threadIdx.x;
    const int lane = tid & 31;
    const int wid  = tid >> 5;
    const int g    = lane >> 2;
    const int tig  = lane & 3;
    const int b    = blockIdx.y;
    const int pt0  = blockIdx.x * TILE_M;
    const __half* hb = h + (size_t)b * PN * PC;

    float* accf  = (float*)smem;
    int*   slist = (int*)(smem + OFF_LIST);
    int*   swcnt = (int*)(smem + OFF_WCNT);

    {
        float2 z = make_float2(0.f, 0.f);
        float2* a2 = (float2*)smem;
#pragma unroll
        for (int i = 0; i < 33; i++) a2[tid + 256 * i] = z;
    }

    const int  gp   = pt0 + tid;
    const bool inr  = gp < PN;
    const size_t gidx = (size_t)b * PN + gp;

    int pref = inr ? g_nbr[gidx] : -1;
    int nidx = -1, rank = 0, cnt = 0;

    auto new_tap = [&](int k) {
        nidx = pref;
        pref = (k + 1 < 27 && inr) ? g_nbr[(size_t)(k + 1) * BN + gidx] : -1;
        unsigned msk = __ballot_sync(0xffffffffu, nidx >= 0);
        if (lane == 0) swcnt[wid] = __popc(msk);
        __syncthreads();
        int base = 0, tot = 0;
#pragma unroll
        for (int j = 0; j < 8; j++) {
            int c = swcnt[j];
            base += (j < wid) ? c : 0;
            tot += c;
        }
        rank = base + __popc(msk & ((1u << lane) - 1u));
        cnt = tot;
        __syncthreads();
    };

    auto issue_w = [&](int k, int ws) {
        const char* src = (const char*)(wt + (size_t)k * 4096);
#pragma unroll
        for (int j = 0; j < 2; j++) {
            int c = tid + j * 256;
            int row = c >> 3, off = (c & 7) * 16;
            uint32_t dst = sbase + OFF_W + ws * 9216 + row * 144 + off;
            asm volatile("cp.async.ca.shared.global [%0],[%1],16;"
                         :: "r"(dst), "l"(src + row * 128 + off));
        }
    };

    auto fill_list = [&](int lo, int st) {
        if (nidx >= 0 && rank >= lo && rank < lo + 64)
            slist[st * 64 + (rank - lo)] = (nidx << 8) | tid;
    };

    auto issue_a = [&](int Rc, int st) {
        int row = tid >> 2, q = tid & 3;
        if (row < Rc) {
            int e = slist[st * 64 + row];
            const char* src = (const char*)(hb + ((size_t)(e >> 8)) * PC) + q * 32;
            uint32_t dst = sbase + OFF_A + st * 9216 + row * 144 + q * 32;
            asm volatile("cp.async.ca.shared.global [%0],[%1],16;" :: "r"(dst), "l"(src));
            asm volatile("cp.async.ca.shared.global [%0],[%1],16;" :: "r"(dst + 16), "l"(src + 16));
        }
        asm volatile("cp.async.commit_group;" ::: "memory");
    };

    uint32_t bw[4][2];
    auto load_b = [&](int ws) {
#pragma unroll
        for (int j = 0; j < 4; j++) {
            uint32_t ad = sbase + OFF_W + ws * 9216 +
                          (uint32_t)(wid * 8 + (lane & 7)) * 144 + j * 32 +
                          ((lane >> 3) & 1) * 16;
            asm volatile("ldmatrix.sync.aligned.m8n8.x2.shared.b16 {%0,%1},[%2];"
                         : "=r"(bw[j][0]), "=r"(bw[j][1]) : "r"(ad));
        }
    };

    auto do_chunk = [&](int st, int Rc) {
        int Mc = (Rc + 15) >> 4;
        uint32_t ab = sbase + OFF_A + st * 9216 + (uint32_t)(lane & 15) * 144 +
                      (lane >> 4) * 16;
        for (int mt = 0; mt < Mc; mt++) {
            uint32_t a[4];
            float c[4] = {0.f, 0.f, 0.f, 0.f};
#pragma unroll
            for (int j = 0; j < 4; j++) {
                asm volatile("ldmatrix.sync.aligned.m8n8.x4.shared.b16 {%0,%1,%2,%3},[%4];"
                             : "=r"(a[0]), "=r"(a[1]), "=r"(a[2]), "=r"(a[3])
                             : "r"(ab + mt * 2304 + j * 32));
                asm volatile(
                    "mma.sync.aligned.m16n8k16.row.col.f32.f16.f16.f32 "
                    "{%0,%1,%2,%3},{%4,%5,%6,%7},{%8,%9},{%0,%1,%2,%3};"
                    : "+f"(c[0]), "+f"(c[1]), "+f"(c[2]), "+f"(c[3])
                    : "r"(a[0]), "r"(a[1]), "r"(a[2]), "r"(a[3]),
                      "r"(bw[j][0]), "r"(bw[j][1]));
            }
            int r0 = mt * 16 + g;
            if (r0 < Rc) {
                int t = slist[st * 64 + r0] & 255;
                float2* p = (float2*)(accf + (size_t)t * ACC_STRIDE + wid * 8 + 2 * tig);
                float2 v = *p; v.x += c[0]; v.y += c[1]; *p = v;
            }
            if (r0 + 8 < Rc) {
                int t = slist[st * 64 + r0 + 8] & 255;
                float2* p = (float2*)(accf + (size_t)t * ACC_STRIDE + wid * 8 + 2 * tig);
                float2 v = *p; v.x += c[2]; v.y += c[3]; *p = v;
            }
        }
    };

    int k = 0;
    new_tap(0);
    while (cnt == 0 && k < 26) { k++; new_tap(k); }
    issue_w(k, 0);
    fill_list(0, 0);
    __syncthreads();
    int firstRc = (cnt < 64) ? cnt : 64;
    issue_a(firstRc, 0);

    int curk = k, curlo = 0, curst = 0, curWst = 0, curRc = firstRc;
    bool curNew = true;
    int tapcnt = cnt;

    while (true) {
        int nRc = 0, nst = curst ^ 1, nWst = curWst, nk = curk, nlo = 0;
        bool nNew = false;
        if (curlo + 64 < tapcnt) {
            nk = curk; nlo = curlo + 64;
            nRc = tapcnt - nlo; if (nRc > 64) nRc = 64;
            fill_list(nlo, nst);
            __syncthreads();
            issue_a(nRc, nst);
        } else {
            int k2 = curk + 1;
            while (k2 < 27) { new_tap(k2); if (cnt > 0) break; k2++; }
            if (k2 < 27) {
                nk = k2; nlo = 0; nNew = true; nWst = curWst ^ 1;
                nRc = (cnt < 64) ? cnt : 64;
                issue_w(k2, nWst);
                fill_list(0, nst);
                __syncthreads();
                issue_a(nRc, nst);
            }
        }
        if (nRc > 0) asm volatile("cp.async.wait_group 1;" ::: "memory");
        else         asm volatile("cp.async.wait_group 0;" ::: "memory");
        __syncthreads();
        if (curNew) load_b(curWst);
        do_chunk(curst, curRc);
        __syncthreads();
        if (nRc == 0) break;
        curk = nk; curlo = nlo; curst = nst; curWst = nWst; curNew = nNew; curRc = nRc;
        if (nNew) tapcnt = cnt;
    }

    const bool doadd = (addsrc != nullptr);
    for (int r32 = 0; r32 < 32; r32++) {
        int row = wid * 32 + r32;
        int p = pt0 + row;
        if (p < PN) {
            float2 v = *(float2*)(accf + (size_t)row * ACC_STRIDE + lane * 2);
            size_t o = ((size_t)b * PN + p) * PC + lane * 2;
            if constexpr (sizeof(OutT) == 4) {
                if (doadd) {
                    float2 a2 = *(const float2*)(addsrc + o);
                    v.x += a2.x; v.y += a2.y;
                }
                *(float2*)((float*)out + o) = v;
            } else {
                *(__half2*)((__half*)out + o) = __floats2half2_rn(v.x, v.y);
            }
        }
    }
}

// ---------------- host orchestration ----------------
extern "C" void kernel_launch(void* const* d_in, const int* in_sizes, int n_in,
                              void* d_out, int out_size) {
    const float* feats  = (const float*)d_in[0];
    const float* Ws     = (const float*)d_in[1];
    const float* gammas = (const float*)d_in[2];
    const float* betas  = (const float*)d_in[3];
    const int*   pos    = (const int*)d_in[4];
    float* x = (float*)d_out;

    __half *h16, *wt16, *tmp16;
    cudaGetSymbolAddress((void**)&h16, g_h16);
    cudaGetSymbolAddress((void**)&wt16, g_wt16);
    cudaGetSymbolAddress((void**)&tmp16, g_tmp16);

    cudaFuncSetAttribute(conv_sp_kernel<float>,
                         cudaFuncAttributeMaxDynamicSharedMemorySize, SMEM_SP);
    cudaFuncSetAttribute(conv_sp_kernel<__half>,
                         cudaFuncAttributeMaxDynamicSharedMemorySize, SMEM_SP);

    prep0_kernel<<<(PB * PD3 + 1023) / 1024, 1024>>>(Ws);
    scatter_lut_kernel<<<(BN + 255) / 256, 256>>>(pos);
    build_nbr_kernel<<<(BN + 255) / 256, 256>>>(pos);

    dim3 cgrid(NTILES, PB);
    const int bnb = (TOTE / 8 + 255) / 256;

    // block 0
    stats_kernel<<<STAT_BLOCKS, 256>>>(feats, gammas + 0 * PC, betas + 0 * PC);
    bnrelu_kernel<<<bnb, 256>>>(feats, h16);
    conv_sp_kernel<__half><<<cgrid, 256, SMEM_SP>>>(
        h16, wt16 + (size_t)0 * 27 * 4096, tmp16, nullptr);
    stats16_kernel<<<STAT_BLOCKS, 256>>>(tmp16, gammas + 1 * PC, betas + 1 * PC);
    bnrelu16_kernel<<<bnb, 256>>>(tmp16, h16);
    conv_sp_kernel<float><<<cgrid, 256, SMEM_SP>>>(
        h16, wt16 + (size_t)1 * 27 * 4096, x, feats);

    // block 1
    stats_kernel<<<STAT_BLOCKS, 256>>>(x, gammas + 2 * PC, betas + 2 * PC);
    bnrelu_kernel<<<bnb, 256>>>(x, h16);
    conv_sp_kernel<__half><<<cgrid, 256, SMEM_SP>>>(
        h16, wt16 + (size_t)2 * 27 * 4096, tmp16, nullptr);
    stats16_kernel<<<STAT_BLOCKS, 256>>>(tmp16, gammas + 3 * PC, betas + 3 * PC);
    bnrelu16_kernel<<<bnb, 256>>>(tmp16, h16);
    conv_sp_kernel<float><<<cgrid, 256, SMEM_SP>>>(
        h16, wt16 + (size_t)3 * 27 * 4096, x, x);
}

// round 15
// speedup vs baseline: 1.0655x; 1.0062x over previous
#include <cuda_runtime.h>
#include <cuda_fp16.h>
#include <cstdint>

// Problem constants
#define PB   2
#define PN   150000
#define PC   64
#define PD   128
#define PD3  (PD*PD*PD)
#define BN   (PB*PN)
#define TOTE (BN*PC)
#define EPSV 1e-4f
#define STAT_BLOCKS 1024

#define TILE_M 256
#define NTILES ((PN + TILE_M - 1) / TILE_M)   // 586

// smem layout (bytes) for sparse conv kernel  (EXACTLY R5/R11/R12)
#define ACC_STRIDE 66
#define OFF_ACC   0
#define OFF_A     67584
#define OFF_W     86016
#define OFF_LIST  104448
#define OFF_WCNT  104960
#define SMEM_SP   105216

// ---------------- device scratch ----------------
__device__ int      g_lut[PB * PD3];
__device__ int      g_nbr[27 * BN];
__device__ __half   g_tmp16[(size_t)BN * PC];       // conv1/3 output (fp16)
__device__ __half   g_h16[(size_t)BN * PC];         // bn_relu output (fp16 conv input)
__device__ __half   g_wt16[4 * 27 * PC * PC];       // W^T fp16 [conv*27][cout][cin]
__device__ float    g_part[2 * STAT_BLOCKS * PC];
__device__ float    g_scale[PC];
__device__ float    g_shift[PC];
__device__ unsigned g_tick;                         // ticket for fused stats0

// ---------------- helpers ----------------
__device__ __forceinline__ uint32_t smem_u32(const void* p) {
    uint32_t a;
    asm("{ .reg .u64 t; cvta.to.shared.u64 t, %1; cvt.u32.u64 %0, t; }" : "=r"(a) : "l"(p));
    return a;
}

__device__ __forceinline__ void finalize_in_block(
    float* red, int t, const float* __restrict__ gamma, const float* __restrict__ beta) {
    int c = t & 63, seg = t >> 6;
    float S = 0.f, Q = 0.f;
    for (int b = seg * 256; b < (seg + 1) * 256; b++) {
        S += g_part[b * 64 + c];
        Q += g_part[STAT_BLOCKS * 64 + b * 64 + c];
    }
    red[t] = S; red[256 + t] = Q;
    __syncthreads();
    if (t < 64) {
        float s = red[t] + red[t + 64] + red[t + 128] + red[t + 192];
        float q = red[256 + t] + red[256 + t + 64] + red[256 + t + 128] + red[256 + t + 192];
        const float inv = 1.0f / (float)BN;
        float mu = s * inv;
        float var = q * inv - mu * mu;
        float rstd = rsqrtf(var + EPSV);
        float sc = rstd * gamma[t];
        g_scale[t] = sc;
        g_shift[t] = beta[t] - mu * sc;
    }
}

// ---------------- launch 0: stats on feats (f32) WITH fused finalize ----------------
__global__ void stats0_fused_kernel(const float* __restrict__ x,
                                    const float* __restrict__ gamma,
                                    const float* __restrict__ beta) {
    __shared__ float red[2048];
    __shared__ int is_last;
    int t = threadIdx.x;
    size_t gid = (size_t)blockIdx.x * 256 + t;
    const float4* x4 = (const float4*)x;
    float4 s = make_float4(0, 0, 0, 0), q = make_float4(0, 0, 0, 0);
    for (size_t i = gid; i < (size_t)TOTE / 4; i += (size_t)256 * STAT_BLOCKS) {
        float4 v = x4[i];
        s.x += v.x; s.y += v.y; s.z += v.z; s.w += v.w;
        q.x += v.x * v.x; q.y += v.y * v.y; q.z += v.z * v.z; q.w += v.w * v.w;
    }
    red[t * 4 + 0] = s.x; red[t * 4 + 1] = s.y; red[t * 4 + 2] = s.z; red[t * 4 + 3] = s.w;
    red[1024 + t * 4 + 0] = q.x; red[1024 + t * 4 + 1] = q.y;
    red[1024 + t * 4 + 2] = q.z; red[1024 + t * 4 + 3] = q.w;
    __syncthreads();
    if (t < 64) {
        int comp = t & 3, grp = t >> 2;
        float S = 0.f, Q = 0.f;
#pragma unroll
        for (int m = 0; m < 16; m++) {
            int o = grp + m * 16;
            S += red[o * 4 + comp];
            Q += red[1024 + o * 4 + comp];
        }
        g_part[blockIdx.x * 64 + t] = S;
        g_part[STAT_BLOCKS * 64 + blockIdx.x * 64 + t] = Q;
    }
    __syncthreads();
    if (t == 0) {
        __threadfence();
        unsigned old = atomicAdd(&g_tick, 1u);
        is_last = (old == STAT_BLOCKS - 1);
        if (is_last) g_tick = 0;
    }
    __syncthreads();
    if (is_last) finalize_in_block(red, t, gamma, beta);
}

// ---------------- launch 1: bnrelu(feats) + scatter_lut + wprep (fused) ----------------
__global__ void bnrelu0_fused_kernel(const float* __restrict__ x, __half* __restrict__ y,
                                     const int* __restrict__ pos,
                                     const float* __restrict__ Ws) {
    int i = blockIdx.x * blockDim.x + threadIdx.x;
    // side job 1: scatter lut (lut pre-filled to -1 via memset)
    if (i < BN) {
        int b = i / PN;
        int code = (pos[3 * i] * PD + pos[3 * i + 1]) * PD + pos[3 * i + 2];
        g_lut[b * PD3 + code] = i - b * PN;
    }
    // side job 2: W^T fp16
    if (i < 4 * 27 * 4096) {
        int mat = i >> 12;
        int co  = (i >> 6) & 63;
        int ci  = i & 63;
        g_wt16[i] = __float2half_rn(Ws[mat * 4096 + ci * 64 + co]);
    }
    if (i >= TOTE / 8) return;
    const float4* x4 = (const float4*)x;
    float4 v0 = x4[2 * i], v1 = x4[2 * i + 1];
    int c8 = i & 7;
    float4 sc0 = ((const float4*)g_scale)[2 * c8], sc1 = ((const float4*)g_scale)[2 * c8 + 1];
    float4 sh0 = ((const float4*)g_shift)[2 * c8], sh1 = ((const float4*)g_shift)[2 * c8 + 1];
    __half2 h[4];
    h[0] = __floats2half2_rn(fmaxf(fmaf(v0.x, sc0.x, sh0.x), 0.f),
                             fmaxf(fmaf(v0.y, sc0.y, sh0.y), 0.f));
    h[1] = __floats2half2_rn(fmaxf(fmaf(v0.z, sc0.z, sh0.z), 0.f),
                             fmaxf(fmaf(v0.w, sc0.w, sh0.w), 0.f));
    h[2] = __floats2half2_rn(fmaxf(fmaf(v1.x, sc1.x, sh1.x), 0.f),
                             fmaxf(fmaf(v1.y, sc1.y, sh1.y), 0.f));
    h[3] = __floats2half2_rn(fmaxf(fmaf(v1.z, sc1.z, sh1.z), 0.f),
                             fmaxf(fmaf(v1.w, sc1.w, sh1.w), 0.f));
    ((uint4*)y)[i] = *(uint4*)h;
}

// ---------------- launch 2: neighbor table ----------------
__global__ void build_nbr_kernel(const int* __restrict__ pos) {
    int i = blockIdx.x * blockDim.x + threadIdx.x;
    if (i >= BN) return;
    int b = i / PN;
    int px = pos[3 * i], py = pos[3 * i + 1], pz = pos[3 * i + 2];
    const int* lutb = g_lut + b * PD3;
#pragma unroll
    for (int k = 0; k < 27; k++) {
        int nx = px + k / 9 - 1, ny = py + (k / 3) % 3 - 1, nz = pz + k % 3 - 1;
        int nidx = -1;
        if (((unsigned)nx < PD) & ((unsigned)ny < PD) & ((unsigned)nz < PD))
            nidx = lutb[(nx * PD + ny) * PD + nz];
        g_nbr[k * BN + i] = nidx;
    }
}

// ---------------- BN kernels (R12, separate finalize) ----------------
__global__ void stats_kernel(const float* __restrict__ x) {
    __shared__ float red[2048];
    int t = threadIdx.x;
    size_t gid = (size_t)blockIdx.x * 256 + t;
    const float4* x4 = (const float4*)x;
    float4 s = make_float4(0, 0, 0, 0), q = make_float4(0, 0, 0, 0);
    for (size_t i = gid; i < (size_t)TOTE / 4; i += (size_t)256 * STAT_BLOCKS) {
        float4 v = x4[i];
        s.x += v.x; s.y += v.y; s.z += v.z; s.w += v.w;
        q.x += v.x * v.x; q.y += v.y * v.y; q.z += v.z * v.z; q.w += v.w * v.w;
    }
    red[t * 4 + 0] = s.x; red[t * 4 + 1] = s.y; red[t * 4 + 2] = s.z; red[t * 4 + 3] = s.w;
    red[1024 + t * 4 + 0] = q.x; red[1024 + t * 4 + 1] = q.y;
    red[1024 + t * 4 + 2] = q.z; red[1024 + t * 4 + 3] = q.w;
    __syncthreads();
    if (t < 64) {
        int comp = t & 3, grp = t >> 2;
        float S = 0.f, Q = 0.f;
#pragma unroll
        for (int m = 0; m < 16; m++) {
            int o = grp + m * 16;
            S += red[o * 4 + comp];
            Q += red[1024 + o * 4 + comp];
        }
        g_part[blockIdx.x * 64 + t] = S;
        g_part[STAT_BLOCKS * 64 + blockIdx.x * 64 + t] = Q;
    }
}

__global__ void stats16_kernel(const __half* __restrict__ x) {
    __shared__ float red[4096];
    int t = threadIdx.x;
    size_t gid = (size_t)blockIdx.x * 256 + t;
    const uint4* x8 = (const uint4*)x;
    float s[8] = {0, 0, 0, 0, 0, 0, 0, 0}, q[8] = {0, 0, 0, 0, 0, 0, 0, 0};
    for (size_t i = gid; i < (size_t)TOTE / 8; i += (size_t)256 * STAT_BLOCKS) {
        uint4 u = x8[i];
        const __half2* h2 = (const __half2*)&u;
#pragma unroll
        for (int j = 0; j < 4; j++) {
            float2 f = __half22float2(h2[j]);
            s[2 * j] += f.x;     q[2 * j] += f.x * f.x;
            s[2 * j + 1] += f.y; q[2 * j + 1] += f.y * f.y;
        }
    }
#pragma unroll
    for (int j = 0; j < 8; j++) { red[t * 8 + j] = s[j]; red[2048 + t * 8 + j] = q[j]; }
    __syncthreads();
    if (t < 64) {
        int grp = t >> 3;
        int sub = t & 7;
        float S = 0.f, Q = 0.f;
#pragma unroll
        for (int m = 0; m < 32; m++) {
            int tt = grp + m * 8;
            S += red[tt * 8 + sub];
            Q += red[2048 + tt * 8 + sub];
        }
        g_part[blockIdx.x * 64 + t] = S;
        g_part[STAT_BLOCKS * 64 + blockIdx.x * 64 + t] = Q;
    }
}

__global__ void finalize_stats_kernel(const float* __restrict__ gamma,
                                      const float* __restrict__ beta) {
    __shared__ float r[512];
    int t = threadIdx.x;
    finalize_in_block(r, t, gamma, beta);
}

__global__ void bnrelu_kernel(const float* __restrict__ x, __half* __restrict__ y) {
    int i = blockIdx.x * blockDim.x + threadIdx.x;
    if (i >= TOTE / 8) return;
    const float4* x4 = (const float4*)x;
    float4 v0 = x4[2 * i], v1 = x4[2 * i + 1];
    int c8 = i & 7;
    float4 sc0 = ((const float4*)g_scale)[2 * c8], sc1 = ((const float4*)g_scale)[2 * c8 + 1];
    float4 sh0 = ((const float4*)g_shift)[2 * c8], sh1 = ((const float4*)g_shift)[2 * c8 + 1];
    __half2 h[4];
    h[0] = __floats2half2_rn(fmaxf(fmaf(v0.x, sc0.x, sh0.x), 0.f),
                             fmaxf(fmaf(v0.y, sc0.y, sh0.y), 0.f));
    h[1] = __floats2half2_rn(fmaxf(fmaf(v0.z, sc0.z, sh0.z), 0.f),
                             fmaxf(fmaf(v0.w, sc0.w, sh0.w), 0.f));
    h[2] = __floats2half2_rn(fmaxf(fmaf(v1.x, sc1.x, sh1.x), 0.f),
                             fmaxf(fmaf(v1.y, sc1.y, sh1.y), 0.f));
    h[3] = __floats2half2_rn(fmaxf(fmaf(v1.z, sc1.z, sh1.z), 0.f),
                             fmaxf(fmaf(v1.w, sc1.w, sh1.w), 0.f));
    ((uint4*)y)[i] = *(uint4*)h;
}

__global__ void bnrelu16_kernel(const __half* __restrict__ x, __half* __restrict__ y) {
    int i = blockIdx.x * blockDim.x + threadIdx.x;
    if (i >= TOTE / 8) return;
    uint4 u = ((const uint4*)x)[i];
    const __half2* h2 = (const __half2*)&u;
    int c8 = i & 7;
    float4 sc0 = ((const float4*)g_scale)[2 * c8], sc1 = ((const float4*)g_scale)[2 * c8 + 1];
    float4 sh0 = ((const float4*)g_shift)[2 * c8], sh1 = ((const float4*)g_shift)[2 * c8 + 1];
    float2 f0 = __half22float2(h2[0]), f1 = __half22float2(h2[1]);
    float2 f2 = __half22float2(h2[2]), f3 = __half22float2(h2[3]);
    __half2 h[4];
    h[0] = __floats2half2_rn(fmaxf(fmaf(f0.x, sc0.x, sh0.x), 0.f),
                             fmaxf(fmaf(f0.y, sc0.y, sh0.y), 0.f));
    h[1] = __floats2half2_rn(fmaxf(fmaf(f1.x, sc0.z, sh0.z), 0.f),
                             fmaxf(fmaf(f1.y, sc0.w, sh0.w), 0.f));
    h[2] = __floats2half2_rn(fmaxf(fmaf(f2.x, sc1.x, sh1.x), 0.f),
                             fmaxf(fmaf(f2.y, sc1.y, sh1.y), 0.f));
    h[3] = __floats2half2_rn(fmaxf(fmaf(f3.x, sc1.z, sh1.z), 0.f),
                             fmaxf(fmaf(f3.y, sc1.w, sh1.w), 0.f));
    ((uint4*)y)[i] = *(uint4*)h;
}

// ---------------- sparse conv (EXACTLY R12) ----------------
template <typename OutT>
__global__ __launch_bounds__(256, 2) void conv_sp_kernel(
    const __half* __restrict__ h, const __half* __restrict__ wt,
    OutT* __restrict__ out, const float* __restrict__ addsrc) {
    extern __shared__ char smem[];
    const uint32_t sbase = smem_u32(smem);
    const int tid  = threadIdx.x;
    const int lane = tid & 31;
    const int wid  = tid >> 5;
    const int g    = lane >> 2;
    const int tig  = lane & 3;
    const int b    = blockIdx.y;
    const int pt0  = blockIdx.x * TILE_M;
    const __half* hb = h + (size_t)b * PN * PC;

    float* accf  = (float*)smem;
    int*   slist = (int*)(smem + OFF_LIST);
    int*   swcnt = (int*)(smem + OFF_WCNT);

    {
        float2 z = make_float2(0.f, 0.f);
        float2* a2 = (float2*)smem;
#pragma unroll
        for (int i = 0; i < 33; i++) a2[tid + 256 * i] = z;
    }

    const int  gp   = pt0 + tid;
    const bool inr  = gp < PN;
    const size_t gidx = (size_t)b * PN + gp;

    int pref = inr ? g_nbr[gidx] : -1;
    int nidx = -1, rank = 0, cnt = 0;

    auto new_tap = [&](int k) {
        nidx = pref;
        pref = (k + 1 < 27 && inr) ? g_nbr[(size_t)(k + 1) * BN + gidx] : -1;
        unsigned msk = __ballot_sync(0xffffffffu, nidx >= 0);
        if (lane == 0) swcnt[wid] = __popc(msk);
        __syncthreads();
        int base = 0, tot = 0;
#pragma unroll
        for (int j = 0; j < 8; j++) {
            int c = swcnt[j];
            base += (j < wid) ? c : 0;
            tot += c;
        }
        rank = base + __popc(msk & ((1u << lane) - 1u));
        cnt = tot;
        __syncthreads();
    };

    auto issue_w = [&](int k, int ws) {
        const char* src = (const char*)(wt + (size_t)k * 4096);
#pragma unroll
        for (int j = 0; j < 2; j++) {
            int c = tid + j * 256;
            int row = c >> 3, off = (c & 7) * 16;
            uint32_t dst = sbase + OFF_W + ws * 9216 + row * 144 + off;
            asm volatile("cp.async.ca.shared.global [%0],[%1],16;"
                         :: "r"(dst), "l"(src + row * 128 + off));
        }
    };

    auto fill_list = [&](int lo, int st) {
        if (nidx >= 0 && rank >= lo && rank < lo + 64)
            slist[st * 64 + (rank - lo)] = (nidx << 8) | tid;
    };

    auto issue_a = [&](int Rc, int st) {
        int row = tid >> 2, q = tid & 3;
        if (row < Rc) {
            int e = slist[st * 64 + row];
            const char* src = (const char*)(hb + ((size_t)(e >> 8)) * PC) + q * 32;
            uint32_t dst = sbase + OFF_A + st * 9216 + row * 144 + q * 32;
            asm volatile("cp.async.ca.shared.global [%0],[%1],16;" :: "r"(dst), "l"(src));
            asm volatile("cp.async.ca.shared.global [%0],[%1],16;" :: "r"(dst + 16), "l"(src + 16));
        }
        asm volatile("cp.async.commit_group;" ::: "memory");
    };

    uint32_t bw[4][2];
    auto load_b = [&](int ws) {
#pragma unroll
        for (int j = 0; j < 4; j++) {
            uint32_t ad = sbase + OFF_W + ws * 9216 +
                          (uint32_t)(wid * 8 + (lane & 7)) * 144 + j * 32 +
                          ((lane >> 3) & 1) * 16;
            asm volatile("ldmatrix.sync.aligned.m8n8.x2.shared.b16 {%0,%1},[%2];"
                         : "=r"(bw[j][0]), "=r"(bw[j][1]) : "r"(ad));
        }
    };

    auto do_chunk = [&](int st, int Rc) {
        int Mc = (Rc + 15) >> 4;
        uint32_t ab = sbase + OFF_A + st * 9216 + (uint32_t)(lane & 15) * 144 +
                      (lane >> 4) * 16;
        for (int mt = 0; mt < Mc; mt++) {
            uint32_t a[4];
            float c[4] = {0.f, 0.f, 0.f, 0.f};
#pragma unroll
            for (int j = 0; j < 4; j++) {
                asm volatile("ldmatrix.sync.aligned.m8n8.x4.shared.b16 {%0,%1,%2,%3},[%4];"
                             : "=r"(a[0]), "=r"(a[1]), "=r"(a[2]), "=r"(a[3])
                             : "r"(ab + mt * 2304 + j * 32));
                asm volatile(
                    "mma.sync.aligned.m16n8k16.row.col.f32.f16.f16.f32 "
                    "{%0,%1,%2,%3},{%4,%5,%6,%7},{%8,%9},{%0,%1,%2,%3};"
                    : "+f"(c[0]), "+f"(c[1]), "+f"(c[2]), "+f"(c[3])
                    : "r"(a[0]), "r"(a[1]), "r"(a[2]), "r"(a[3]),
                      "r"(bw[j][0]), "r"(bw[j][1]));
            }
            int r0 = mt * 16 + g;
            if (r0 < Rc) {
                int t = slist[st * 64 + r0] & 255;
                float2* p = (float2*)(accf + (size_t)t * ACC_STRIDE + wid * 8 + 2 * tig);
                float2 v = *p; v.x += c[0]; v.y += c[1]; *p = v;
            }
            if (r0 + 8 < Rc) {
                int t = slist[st * 64 + r0 + 8] & 255;
                float2* p = (float2*)(accf + (size_t)t * ACC_STRIDE + wid * 8 + 2 * tig);
                float2 v = *p; v.x += c[2]; v.y += c[3]; *p = v;
            }
        }
    };

    int k = 0;
    new_tap(0);
    while (cnt == 0 && k < 26) { k++; new_tap(k); }
    issue_w(k, 0);
    fill_list(0, 0);
    __syncthreads();
    int firstRc = (cnt < 64) ? cnt : 64;
    issue_a(firstRc, 0);

    int curk = k, curlo = 0, curst = 0, curWst = 0, curRc = firstRc;
    bool curNew = true;
    int tapcnt = cnt;

    while (true) {
        int nRc = 0, nst = curst ^ 1, nWst = curWst, nk = curk, nlo = 0;
        bool nNew = false;
        if (curlo + 64 < tapcnt) {
            nk = curk; nlo = curlo + 64;
            nRc = tapcnt - nlo; if (nRc > 64) nRc = 64;
            fill_list(nlo, nst);
            __syncthreads();
            issue_a(nRc, nst);
        } else {
            int k2 = curk + 1;
            while (k2 < 27) { new_tap(k2); if (cnt > 0) break; k2++; }
            if (k2 < 27) {
                nk = k2; nlo = 0; nNew = true; nWst = curWst ^ 1;
                nRc = (cnt < 64) ? cnt : 64;
                issue_w(k2, nWst);
                fill_list(0, nst);
                __syncthreads();
                issue_a(nRc, nst);
            }
        }
        if (nRc > 0) asm volatile("cp.async.wait_group 1;" ::: "memory");
        else         asm volatile("cp.async.wait_group 0;" ::: "memory");
        __syncthreads();
        if (curNew) load_b(curWst);
        do_chunk(curst, curRc);
        __syncthreads();
        if (nRc == 0) break;
        curk = nk; curlo = nlo; curst = nst; curWst = nWst; curNew = nNew; curRc = nRc;
        if (nNew) tapcnt = cnt;
    }

    const bool doadd = (addsrc != nullptr);
    for (int r32 = 0; r32 < 32; r32++) {
        int row = wid * 32 + r32;
        int p = pt0 + row;
        if (p < PN) {
            float2 v = *(float2*)(accf + (size_t)row * ACC_STRIDE + lane * 2);
            size_t o = ((size_t)b * PN + p) * PC + lane * 2;
            if constexpr (sizeof(OutT) == 4) {
                if (doadd) {
                    float2 a2 = *(const float2*)(addsrc + o);
                    v.x += a2.x; v.y += a2.y;
                }
                *(float2*)((float*)out + o) = v;
            } else {
                *(__half2*)((__half*)out + o) = __floats2half2_rn(v.x, v.y);
            }
        }
    }
}

// ---------------- host orchestration ----------------
extern "C" void kernel_launch(void* const* d_in, const int* in_sizes, int n_in,
                              void* d_out, int out_size) {
    const float* feats  = (const float*)d_in[0];
    const float* Ws     = (const float*)d_in[1];
    const float* gammas = (const float*)d_in[2];
    const float* betas  = (const float*)d_in[3];
    const int*   pos    = (const int*)d_in[4];
    float* x = (float*)d_out;

    __half *h16, *wt16, *tmp16;
    int* lut;
    cudaGetSymbolAddress((void**)&h16, g_h16);
    cudaGetSymbolAddress((void**)&wt16, g_wt16);
    cudaGetSymbolAddress((void**)&tmp16, g_tmp16);
    cudaGetSymbolAddress((void**)&lut, g_lut);

    cudaFuncSetAttribute(conv_sp_kernel<float>,
                         cudaFuncAttributeMaxDynamicSharedMemorySize, SMEM_SP);
    cudaFuncSetAttribute(conv_sp_kernel<__half>,
                         cudaFuncAttributeMaxDynamicSharedMemorySize, SMEM_SP);

    // non-kernel node: lut = -1
    cudaMemsetAsync(lut, 0xFF, sizeof(int) * PB * PD3, 0);

    dim3 cgrid(NTILES, PB);
    const int bnb = (TOTE / 8 + 255) / 256;

    // launch 0-2: stats0(fused finalize), bnrelu0(+scatter+wprep), nbr
    stats0_fused_kernel<<<STAT_BLOCKS, 256>>>(feats, gammas + 0 * PC, betas + 0 * PC);
    bnrelu0_fused_kernel<<<bnb, 256>>>(feats, h16, pos, Ws);
    build_nbr_kernel<<<(BN + 255) / 256, 256>>>(pos);

    // launch 3: conv (profiled)
    conv_sp_kernel<__half><<<cgrid, 256, SMEM_SP>>>(
        h16, wt16 + (size_t)0 * 27 * 4096, tmp16, nullptr);
    stats16_kernel<<<STAT_BLOCKS, 256>>>(tmp16);
    finalize_stats_kernel<<<1, 256>>>(gammas + 1 * PC, betas + 1 * PC);
    bnrelu16_kernel<<<bnb, 256>>>(tmp16, h16);
    conv_sp_kernel<float><<<cgrid, 256, SMEM_SP>>>(
        h16, wt16 + (size_t)1 * 27 * 4096, x, feats);

    // block 1
    stats_kernel<<<STAT_BLOCKS, 256>>>(x);
    finalize_stats_kernel<<<1, 256>>>(gammas + 2 * PC, betas + 2 * PC);
    bnrelu_kernel<<<bnb, 256>>>(x, h16);
    conv_sp_kernel<__half><<<cgrid, 256, SMEM_SP>>>(
        h16, wt16 + (size_t)2 * 27 * 4096, tmp16, nullptr);
    stats16_kernel<<<STAT_BLOCKS, 256>>>(tmp16);
    finalize_stats_kernel<<<1, 256>>>(gammas + 3 * PC, betas + 3 * PC);
    bnrelu16_kernel<<<bnb, 256>>>(tmp16, h16);
    conv_sp_kernel<float><<<cgrid, 256, SMEM_SP>>>(
        h16, wt16 + (size_t)3 * 27 * 4096, x, x);
}

// round 16
// speedup vs baseline: 1.0911x; 1.0240x over previous
#include <cuda_runtime.h>
#include <cuda_fp16.h>
#include <cstdint>

// Problem constants
#define PB   2
#define PN   150000
#define PC   64
#define PD   128
#define PD3  (PD*PD*PD)
#define BN   (PB*PN)
#define TOTE (BN*PC)
#define EPSV 1e-4f
#define STAT_BLOCKS 1024

#define TILE_M 256
#define NTILES ((PN + TILE_M - 1) / TILE_M)   // 586

// smem layout (bytes) for sparse conv kernel
#define ACC_STRIDE 66
#define OFF_ACC   0
#define OFF_A     67584
#define OFF_W     86016
#define OFF_LIST  104448
#define OFF_WCNT  104960
#define SMEM_SP   105216

// ---------------- device scratch ----------------
__device__ int      g_lut[PB * PD3];
__device__ int      g_nbr[27 * BN];
__device__ __half   g_tmp16[(size_t)BN * PC];
__device__ __half   g_h16[(size_t)BN * PC];
__device__ __half   g_wt16[4 * 27 * PC * PC];
__device__ float    g_part[2 * STAT_BLOCKS * PC];
__device__ float    g_scale[PC];
__device__ float    g_shift[PC];
__device__ unsigned g_tick;

// ---------------- helpers ----------------
__device__ __forceinline__ uint32_t smem_u32(const void* p) {
    uint32_t a;
    asm("{ .reg .u64 t; cvta.to.shared.u64 t, %1; cvt.u32.u64 %0, t; }" : "=r"(a) : "l"(p));
    return a;
}

__device__ __forceinline__ void finalize_in_block(
    float* red, int t, const float* __restrict__ gamma, const float* __restrict__ beta) {
    int c = t & 63, seg = t >> 6;
    float S = 0.f, Q = 0.f;
    for (int b = seg * 256; b < (seg + 1) * 256; b++) {
        S += g_part[b * 64 + c];
        Q += g_part[STAT_BLOCKS * 64 + b * 64 + c];
    }
    red[t] = S; red[256 + t] = Q;
    __syncthreads();
    if (t < 64) {
        float s = red[t] + red[t + 64] + red[t + 128] + red[t + 192];
        float q = red[256 + t] + red[256 + t + 64] + red[256 + t + 128] + red[256 + t + 192];
        const float inv = 1.0f / (float)BN;
        float mu = s * inv;
        float var = q * inv - mu * mu;
        float rstd = rsqrtf(var + EPSV);
        float sc = rstd * gamma[t];
        g_scale[t] = sc;
        g_shift[t] = beta[t] - mu * sc;
    }
}

// ---------------- launch 0: stats on feats (f32) WITH fused finalize ----------------
__global__ void stats0_fused_kernel(const float* __restrict__ x,
                                    const float* __restrict__ gamma,
                                    const float* __restrict__ beta) {
    __shared__ float red[2048];
    __shared__ int is_last;
    int t = threadIdx.x;
    size_t gid = (size_t)blockIdx.x * 256 + t;
    const float4* x4 = (const float4*)x;
    float4 s = make_float4(0, 0, 0, 0), q = make_float4(0, 0, 0, 0);
    for (size_t i = gid; i < (size_t)TOTE / 4; i += (size_t)256 * STAT_BLOCKS) {
        float4 v = x4[i];
        s.x += v.x; s.y += v.y; s.z += v.z; s.w += v.w;
        q.x += v.x * v.x; q.y += v.y * v.y; q.z += v.z * v.z; q.w += v.w * v.w;
    }
    red[t * 4 + 0] = s.x; red[t * 4 + 1] = s.y; red[t * 4 + 2] = s.z; red[t * 4 + 3] = s.w;
    red[1024 + t * 4 + 0] = q.x; red[1024 + t * 4 + 1] = q.y;
    red[1024 + t * 4 + 2] = q.z; red[1024 + t * 4 + 3] = q.w;
    __syncthreads();
    if (t < 64) {
        int comp = t & 3, grp = t >> 2;
        float S = 0.f, Q = 0.f;
#pragma unroll
        for (int m = 0; m < 16; m++) {
            int o = grp + m * 16;
            S += red[o * 4 + comp];
            Q += red[1024 + o * 4 + comp];
        }
        g_part[blockIdx.x * 64 + t] = S;
        g_part[STAT_BLOCKS * 64 + blockIdx.x * 64 + t] = Q;
    }
    __syncthreads();
    if (t == 0) {
        __threadfence();
        unsigned old = atomicAdd(&g_tick, 1u);
        is_last = (old == STAT_BLOCKS - 1);
        if (is_last) g_tick = 0;
    }
    __syncthreads();
    if (is_last) finalize_in_block(red, t, gamma, beta);
}

// ---------------- launch 1: bnrelu(feats) + scatter_lut + wprep ----------------
__global__ void bnrelu0_fused_kernel(const float* __restrict__ x, __half* __restrict__ y,
                                     const int* __restrict__ pos,
                                     const float* __restrict__ Ws) {
    int i = blockIdx.x * blockDim.x + threadIdx.x;
    if (i < BN) {
        int b = i / PN;
        int code = (pos[3 * i] * PD + pos[3 * i + 1]) * PD + pos[3 * i + 2];
        g_lut[b * PD3 + code] = i - b * PN;
    }
    if (i < 4 * 27 * 4096) {
        int mat = i >> 12;
        int co  = (i >> 6) & 63;
        int ci  = i & 63;
        g_wt16[i] = __float2half_rn(Ws[mat * 4096 + ci * 64 + co]);
    }
    if (i >= TOTE / 8) return;
    const float4* x4 = (const float4*)x;
    float4 v0 = x4[2 * i], v1 = x4[2 * i + 1];
    int c8 = i & 7;
    float4 sc0 = ((const float4*)g_scale)[2 * c8], sc1 = ((const float4*)g_scale)[2 * c8 + 1];
    float4 sh0 = ((const float4*)g_shift)[2 * c8], sh1 = ((const float4*)g_shift)[2 * c8 + 1];
    __half2 h[4];
    h[0] = __floats2half2_rn(fmaxf(fmaf(v0.x, sc0.x, sh0.x), 0.f),
                             fmaxf(fmaf(v0.y, sc0.y, sh0.y), 0.f));
    h[1] = __floats2half2_rn(fmaxf(fmaf(v0.z, sc0.z, sh0.z), 0.f),
                             fmaxf(fmaf(v0.w, sc0.w, sh0.w), 0.f));
    h[2] = __floats2half2_rn(fmaxf(fmaf(v1.x, sc1.x, sh1.x), 0.f),
                             fmaxf(fmaf(v1.y, sc1.y, sh1.y), 0.f));
    h[3] = __floats2half2_rn(fmaxf(fmaf(v1.z, sc1.z, sh1.z), 0.f),
                             fmaxf(fmaf(v1.w, sc1.w, sh1.w), 0.f));
    ((uint4*)y)[i] = *(uint4*)h;
}

// ---------------- launch 2: neighbor table ----------------
__global__ void build_nbr_kernel(const int* __restrict__ pos) {
    int i = blockIdx.x * blockDim.x + threadIdx.x;
    if (i >= BN) return;
    int b = i / PN;
    int px = pos[3 * i], py = pos[3 * i + 1], pz = pos[3 * i + 2];
    const int* lutb = g_lut + b * PD3;
#pragma unroll
    for (int k = 0; k < 27; k++) {
        int nx = px + k / 9 - 1, ny = py + (k / 3) % 3 - 1, nz = pz + k % 3 - 1;
        int nidx = -1;
        if (((unsigned)nx < PD) & ((unsigned)ny < PD) & ((unsigned)nz < PD))
            nidx = lutb[(nx * PD + ny) * PD + nz];
        g_nbr[k * BN + i] = nidx;
    }
}

// ---------------- BN kernels ----------------
__global__ void stats_kernel(const float* __restrict__ x) {
    __shared__ float red[2048];
    int t = threadIdx.x;
    size_t gid = (size_t)blockIdx.x * 256 + t;
    const float4* x4 = (const float4*)x;
    float4 s = make_float4(0, 0, 0, 0), q = make_float4(0, 0, 0, 0);
    for (size_t i = gid; i < (size_t)TOTE / 4; i += (size_t)256 * STAT_BLOCKS) {
        float4 v = x4[i];
        s.x += v.x; s.y += v.y; s.z += v.z; s.w += v.w;
        q.x += v.x * v.x; q.y += v.y * v.y; q.z += v.z * v.z; q.w += v.w * v.w;
    }
    red[t * 4 + 0] = s.x; red[t * 4 + 1] = s.y; red[t * 4 + 2] = s.z; red[t * 4 + 3] = s.w;
    red[1024 + t * 4 + 0] = q.x; red[1024 + t * 4 + 1] = q.y;
    red[1024 + t * 4 + 2] = q.z; red[1024 + t * 4 + 3] = q.w;
    __syncthreads();
    if (t < 64) {
        int comp = t & 3, grp = t >> 2;
        float S = 0.f, Q = 0.f;
#pragma unroll
        for (int m = 0; m < 16; m++) {
            int o = grp + m * 16;
            S += red[o * 4 + comp];
            Q += red[1024 + o * 4 + comp];
        }
        g_part[blockIdx.x * 64 + t] = S;
        g_part[STAT_BLOCKS * 64 + blockIdx.x * 64 + t] = Q;
    }
}

__global__ void stats16_kernel(const __half* __restrict__ x) {
    __shared__ float red[4096];
    int t = threadIdx.x;
    size_t gid = (size_t)blockIdx.x * 256 + t;
    const uint4* x8 = (const uint4*)x;
    float s[8] = {0, 0, 0, 0, 0, 0, 0, 0}, q[8] = {0, 0, 0, 0, 0, 0, 0, 0};
    for (size_t i = gid; i < (size_t)TOTE / 8; i += (size_t)256 * STAT_BLOCKS) {
        uint4 u = x8[i];
        const __half2* h2 = (const __half2*)&u;
#pragma unroll
        for (int j = 0; j < 4; j++) {
            float2 f = __half22float2(h2[j]);
            s[2 * j] += f.x;     q[2 * j] += f.x * f.x;
            s[2 * j + 1] += f.y; q[2 * j + 1] += f.y * f.y;
        }
    }
#pragma unroll
    for (int j = 0; j < 8; j++) { red[t * 8 + j] = s[j]; red[2048 + t * 8 + j] = q[j]; }
    __syncthreads();
    if (t < 64) {
        int grp = t >> 3;
        int sub = t & 7;
        float S = 0.f, Q = 0.f;
#pragma unroll
        for (int m = 0; m < 32; m++) {
            int tt = grp + m * 8;
            S += red[tt * 8 + sub];
            Q += red[2048 + tt * 8 + sub];
        }
        g_part[blockIdx.x * 64 + t] = S;
        g_part[STAT_BLOCKS * 64 + blockIdx.x * 64 + t] = Q;
    }
}

__global__ void finalize_stats_kernel(const float* __restrict__ gamma,
                                      const float* __restrict__ beta) {
    __shared__ float r[512];
    int t = threadIdx.x;
    finalize_in_block(r, t, gamma, beta);
}

__global__ void bnrelu_kernel(const float* __restrict__ x, __half* __restrict__ y) {
    int i = blockIdx.x * blockDim.x + threadIdx.x;
    if (i >= TOTE / 8) return;
    const float4* x4 = (const float4*)x;
    float4 v0 = x4[2 * i], v1 = x4[2 * i + 1];
    int c8 = i & 7;
    float4 sc0 = ((const float4*)g_scale)[2 * c8], sc1 = ((const float4*)g_scale)[2 * c8 + 1];
    float4 sh0 = ((const float4*)g_shift)[2 * c8], sh1 = ((const float4*)g_shift)[2 * c8 + 1];
    __half2 h[4];
    h[0] = __floats2half2_rn(fmaxf(fmaf(v0.x, sc0.x, sh0.x), 0.f),
                             fmaxf(fmaf(v0.y, sc0.y, sh0.y), 0.f));
    h[1] = __floats2half2_rn(fmaxf(fmaf(v0.z, sc0.z, sh0.z), 0.f),
                             fmaxf(fmaf(v0.w, sc0.w, sh0.w), 0.f));
    h[2] = __floats2half2_rn(fmaxf(fmaf(v1.x, sc1.x, sh1.x), 0.f),
                             fmaxf(fmaf(v1.y, sc1.y, sh1.y), 0.f));
    h[3] = __floats2half2_rn(fmaxf(fmaf(v1.z, sc1.z, sh1.z), 0.f),
                             fmaxf(fmaf(v1.w, sc1.w, sh1.w), 0.f));
    ((uint4*)y)[i] = *(uint4*)h;
}

__global__ void bnrelu16_kernel(const __half* __restrict__ x, __half* __restrict__ y) {
    int i = blockIdx.x * blockDim.x + threadIdx.x;
    if (i >= TOTE / 8) return;
    uint4 u = ((const uint4*)x)[i];
    const __half2* h2 = (const __half2*)&u;
    int c8 = i & 7;
    float4 sc0 = ((const float4*)g_scale)[2 * c8], sc1 = ((const float4*)g_scale)[2 * c8 + 1];
    float4 sh0 = ((const float4*)g_shift)[2 * c8], sh1 = ((const float4*)g_shift)[2 * c8 + 1];
    float2 f0 = __half22float2(h2[0]), f1 = __half22float2(h2[1]);
    float2 f2 = __half22float2(h2[2]), f3 = __half22float2(h2[3]);
    __half2 h[4];
    h[0] = __floats2half2_rn(fmaxf(fmaf(f0.x, sc0.x, sh0.x), 0.f),
                             fmaxf(fmaf(f0.y, sc0.y, sh0.y), 0.f));
    h[1] = __floats2half2_rn(fmaxf(fmaf(f1.x, sc0.z, sh0.z), 0.f),
                             fmaxf(fmaf(f1.y, sc0.w, sh0.w), 0.f));
    h[2] = __floats2half2_rn(fmaxf(fmaf(f2.x, sc1.x, sh1.x), 0.f),
                             fmaxf(fmaf(f2.y, sc1.y, sh1.y), 0.f));
    h[3] = __floats2half2_rn(fmaxf(fmaf(f3.x, sc1.z, sh1.z), 0.f),
                             fmaxf(fmaf(f3.y, sc1.w, sh1.w), 0.f));
    ((uint4*)y)[i] = *(uint4*)h;
}

// ---------------- sparse conv: R12 structure, 4(N)x2(M) warp remap ----------------
// warp w: nh = w&3 -> output cols nh*16..+15 (two n8 MMAs); mh = w>>2 -> row half
// (m16 tiles 2mh, 2mh+1). A fragments read by 4 warps (was 8); B by 2 (was 1).
// Acc ownership (row-half x col-slice) stays exclusive -> identical accumulation.
template <typename OutT>
__global__ __launch_bounds__(256, 2) void conv_sp_kernel(
    const __half* __restrict__ h, const __half* __restrict__ wt,
    OutT* __restrict__ out, const float* __restrict__ addsrc) {
    extern __shared__ char smem[];
    const uint32_t sbase = smem_u32(smem);
    const int tid  = threadIdx.x;
    const int lane = tid & 31;
    const int wid  = tid >> 5;
    const int g    = lane >> 2;
    const int tig  = lane & 3;
    const int nh   = wid & 3;      // n16 slice
    const int mh   = wid >> 2;     // row half
    const int b    = blockIdx.y;
    const int pt0  = blockIdx.x * TILE_M;
    const __half* hb = h + (size_t)b * PN * PC;

    float* accf  = (float*)smem;
    int*   slist = (int*)(smem + OFF_LIST);
    int*   swcnt = (int*)(smem + OFF_WCNT);

    {
        float2 z = make_float2(0.f, 0.f);
        float2* a2 = (float2*)smem;
#pragma unroll
        for (int i = 0; i < 33; i++) a2[tid + 256 * i] = z;
    }

    const int  gp   = pt0 + tid;
    const bool inr  = gp < PN;
    const size_t gidx = (size_t)b * PN + gp;

    int pref = inr ? g_nbr[gidx] : -1;
    int nidx = -1, rank = 0, cnt = 0;

    auto new_tap = [&](int k) {
        nidx = pref;
        pref = (k + 1 < 27 && inr) ? g_nbr[(size_t)(k + 1) * BN + gidx] : -1;
        unsigned msk = __ballot_sync(0xffffffffu, nidx >= 0);
        if (lane == 0) swcnt[wid] = __popc(msk);
        __syncthreads();
        int base = 0, tot = 0;
#pragma unroll
        for (int j = 0; j < 8; j++) {
            int c = swcnt[j];
            base += (j < wid) ? c : 0;
            tot += c;
        }
        rank = base + __popc(msk & ((1u << lane) - 1u));
        cnt = tot;
        __syncthreads();
    };

    auto issue_w = [&](int k, int ws) {
        const char* src = (const char*)(wt + (size_t)k * 4096);
#pragma unroll
        for (int j = 0; j < 2; j++) {
            int c = tid + j * 256;
            int row = c >> 3, off = (c & 7) * 16;
            uint32_t dst = sbase + OFF_W + ws * 9216 + row * 144 + off;
            asm volatile("cp.async.ca.shared.global [%0],[%1],16;"
                         :: "r"(dst), "l"(src + row * 128 + off));
        }
    };

    auto fill_list = [&](int lo, int st) {
        if (nidx >= 0 && rank >= lo && rank < lo + 64)
            slist[st * 64 + (rank - lo)] = (nidx << 8) | tid;
    };

    auto issue_a = [&](int Rc, int st) {
        int row = tid >> 2, q = tid & 3;
        if (row < Rc) {
            int e = slist[st * 64 + row];
            const char* src = (const char*)(hb + ((size_t)(e >> 8)) * PC) + q * 32;
            uint32_t dst = sbase + OFF_A + st * 9216 + row * 144 + q * 32;
            asm volatile("cp.async.ca.shared.global [%0],[%1],16;" :: "r"(dst), "l"(src));
            asm volatile("cp.async.ca.shared.global [%0],[%1],16;" :: "r"(dst + 16), "l"(src + 16));
        }
        asm volatile("cp.async.commit_group;" ::: "memory");
    };

    // B fragments: per k16 step j, two n8 slices (bw[j][0..1] = n8 lo, [2..3] = n8 hi)
    uint32_t bw[4][4];
    auto load_b = [&](int ws) {
        const uint32_t brow = (uint32_t)(nh * 16 + ((lane >> 4) & 1) * 8 + (lane & 7)) * 144 +
                              ((lane >> 3) & 1) * 16;
#pragma unroll
        for (int j = 0; j < 4; j++) {
            uint32_t ad = sbase + OFF_W + ws * 9216 + brow + j * 32;
            asm volatile("ldmatrix.sync.aligned.m8n8.x4.shared.b16 {%0,%1,%2,%3},[%4];"
                         : "=r"(bw[j][0]), "=r"(bw[j][1]), "=r"(bw[j][2]), "=r"(bw[j][3])
                         : "r"(ad));
        }
    };

    auto do_chunk = [&](int st, int Rc) {
        uint32_t ab = sbase + OFF_A + st * 9216 + (uint32_t)(lane & 15) * 144 +
                      (lane >> 4) * 16;
        const int colb = nh * 16 + 2 * tig;
#pragma unroll
        for (int mtt = 0; mtt < 2; mtt++) {
            int mt = mh * 2 + mtt;
            if (mt * 16 >= Rc) break;
            uint32_t a[4];
            float c0[4] = {0.f, 0.f, 0.f, 0.f};
            float c1[4] = {0.f, 0.f, 0.f, 0.f};
#pragma unroll
            for (int j = 0; j < 4; j++) {
                asm volatile("ldmatrix.sync.aligned.m8n8.x4.shared.b16 {%0,%1,%2,%3},[%4];"
                             : "=r"(a[0]), "=r"(a[1]), "=r"(a[2]), "=r"(a[3])
                             : "r"(ab + mt * 2304 + j * 32));
                asm volatile(
                    "mma.sync.aligned.m16n8k16.row.col.f32.f16.f16.f32 "
                    "{%0,%1,%2,%3},{%4,%5,%6,%7},{%8,%9},{%0,%1,%2,%3};"
                    : "+f"(c0[0]), "+f"(c0[1]), "+f"(c0[2]), "+f"(c0[3])
                    : "r"(a[0]), "r"(a[1]), "r"(a[2]), "r"(a[3]),
                      "r"(bw[j][0]), "r"(bw[j][1]));
                asm volatile(
                    "mma.sync.aligned.m16n8k16.row.col.f32.f16.f16.f32 "
                    "{%0,%1,%2,%3},{%4,%5,%6,%7},{%8,%9},{%0,%1,%2,%3};"
                    : "+f"(c1[0]), "+f"(c1[1]), "+f"(c1[2]), "+f"(c1[3])
                    : "r"(a[0]), "r"(a[1]), "r"(a[2]), "r"(a[3]),
                      "r"(bw[j][2]), "r"(bw[j][3]));
            }
            int r0 = mt * 16 + g;
            if (r0 < Rc) {
                int t = slist[st * 64 + r0] & 255;
                float* base = accf + (size_t)t * ACC_STRIDE + colb;
                float2* p0 = (float2*)base;
                float2 v0 = *p0; v0.x += c0[0]; v0.y += c0[1]; *p0 = v0;
                float2* p1 = (float2*)(base + 8);
                float2 v1 = *p1; v1.x += c1[0]; v1.y += c1[1]; *p1 = v1;
            }
            if (r0 + 8 < Rc) {
                int t = slist[st * 64 + r0 + 8] & 255;
                float* base = accf + (size_t)t * ACC_STRIDE + colb;
                float2* p0 = (float2*)base;
                float2 v0 = *p0; v0.x += c0[2]; v0.y += c0[3]; *p0 = v0;
                float2* p1 = (float2*)(base + 8);
                float2 v1 = *p1; v1.x += c1[2]; v1.y += c1[3]; *p1 = v1;
            }
        }
    };

    int k = 0;
    new_tap(0);
    while (cnt == 0 && k < 26) { k++; new_tap(k); }
    issue_w(k, 0);
    fill_list(0, 0);
    __syncthreads();
    int firstRc = (cnt < 64) ? cnt : 64;
    issue_a(firstRc, 0);

    int curk = k, curlo = 0, curst = 0, curWst = 0, curRc = firstRc;
    bool curNew = true;
    int tapcnt = cnt;

    while (true) {
        int nRc = 0, nst = curst ^ 1, nWst = curWst, nk = curk, nlo = 0;
        bool nNew = false;
        if (curlo + 64 < tapcnt) {
            nk = curk; nlo = curlo + 64;
            nRc = tapcnt - nlo; if (nRc > 64) nRc = 64;
            fill_list(nlo, nst);
            __syncthreads();
            issue_a(nRc, nst);
        } else {
            int k2 = curk + 1;
            while (k2 < 27) { new_tap(k2); if (cnt > 0) break; k2++; }
            if (k2 < 27) {
                nk = k2; nlo = 0; nNew = true; nWst = curWst ^ 1;
                nRc = (cnt < 64) ? cnt : 64;
                issue_w(k2, nWst);
                fill_list(0, nst);
                __syncthreads();
                issue_a(nRc, nst);
            }
        }
        if (nRc > 0) asm volatile("cp.async.wait_group 1;" ::: "memory");
        else         asm volatile("cp.async.wait_group 0;" ::: "memory");
        __syncthreads();
        if (curNew) load_b(curWst);
        do_chunk(curst, curRc);
        __syncthreads();
        if (nRc == 0) break;
        curk = nk; curlo = nlo; curst = nst; curWst = nWst; curNew = nNew; curRc = nRc;
        if (nNew) tapcnt = cnt;
    }

    const bool doadd = (addsrc != nullptr);
    for (int r32 = 0; r32 < 32; r32++) {
        int row = wid * 32 + r32;
        int p = pt0 + row;
        if (p < PN) {
            float2 v = *(float2*)(accf + (size_t)row * ACC_STRIDE + lane * 2);
            size_t o = ((size_t)b * PN + p) * PC + lane * 2;
            if constexpr (sizeof(OutT) == 4) {
                if (doadd) {
                    float2 a2 = *(const float2*)(addsrc + o);
                    v.x += a2.x; v.y += a2.y;
                }
                *(float2*)((float*)out + o) = v;
            } else {
                *(__half2*)((__half*)out + o) = __floats2half2_rn(v.x, v.y);
            }
        }
    }
}

// ---------------- host orchestration ----------------
extern "C" void kernel_launch(void* const* d_in, const int* in_sizes, int n_in,
                              void* d_out, int out_size) {
    const float* feats  = (const float*)d_in[0];
    const float* Ws     = (const float*)d_in[1];
    const float* gammas = (const float*)d_in[2];
    const float* betas  = (const float*)d_in[3];
    const int*   pos    = (const int*)d_in[4];
    float* x = (float*)d_out;

    __half *h16, *wt16, *tmp16;
    int* lut;
    cudaGetSymbolAddress((void**)&h16, g_h16);
    cudaGetSymbolAddress((void**)&wt16, g_wt16);
    cudaGetSymbolAddress((void**)&tmp16, g_tmp16);
    cudaGetSymbolAddress((void**)&lut, g_lut);

    cudaFuncSetAttribute(conv_sp_kernel<float>,
                         cudaFuncAttributeMaxDynamicSharedMemorySize, SMEM_SP);
    cudaFuncSetAttribute(conv_sp_kernel<__half>,
                         cudaFuncAttributeMaxDynamicSharedMemorySize, SMEM_SP);

    cudaMemsetAsync(lut, 0xFF, sizeof(int) * PB * PD3, 0);

    dim3 cgrid(NTILES, PB);
    const int bnb = (TOTE / 8 + 255) / 256;

    stats0_fused_kernel<<<STAT_BLOCKS, 256>>>(feats, gammas + 0 * PC, betas + 0 * PC);
    bnrelu0_fused_kernel<<<bnb, 256>>>(feats, h16, pos, Ws);
    build_nbr_kernel<<<(BN + 255) / 256, 256>>>(pos);

    // launch 3: conv (profiled)
    conv_sp_kernel<__half><<<cgrid, 256, SMEM_SP>>>(
        h16, wt16 + (size_t)0 * 27 * 4096, tmp16, nullptr);
    stats16_kernel<<<STAT_BLOCKS, 256>>>(tmp16);
    finalize_stats_kernel<<<1, 256>>>(gammas + 1 * PC, betas + 1 * PC);
    bnrelu16_kernel<<<bnb, 256>>>(tmp16, h16);
    conv_sp_kernel<float><<<cgrid, 256, SMEM_SP>>>(
        h16, wt16 + (size_t)1 * 27 * 4096, x, feats);

    stats_kernel<<<STAT_BLOCKS, 256>>>(x);
    finalize_stats_kernel<<<1, 256>>>(gammas + 2 * PC, betas + 2 * PC);
    bnrelu_kernel<<<bnb, 256>>>(x, h16);
    conv_sp_kernel<__half><<<cgrid, 256, SMEM_SP>>>(
        h16, wt16 + (size_t)2 * 27 * 4096, tmp16, nullptr);
    stats16_kernel<<<STAT_BLOCKS, 256>>>(tmp16);
    finalize_stats_kernel<<<1, 256>>>(gammas + 3 * PC, betas + 3 * PC);
    bnrelu16_kernel<<<bnb, 256>>>(tmp16, h16);
    conv_sp_kernel<float><<<cgrid, 256, SMEM_SP>>>(
        h16, wt16 + (size_t)3 * 27 * 4096, x, x);
}

// round 17
// speedup vs baseline: 1.1439x; 1.0484x over previous
#include <cuda_runtime.h>
#include <cuda_fp16.h>
#include <cstdint>

// Problem constants
#define PB   2
#define PN   150000
#define PC   64
#define PD   128
#define PD3  (PD*PD*PD)
#define BN   (PB*PN)
#define TOTE (BN*PC)
#define EPSV 1e-4f
#define STAT_BLOCKS 1024

#define TILE_M 256
#define NTILES ((PN + TILE_M - 1) / TILE_M)   // 586

// smem layout (bytes) for sparse conv kernel
#define ACC_STRIDE 66
#define OFF_ACC   0
#define OFF_A     67584
#define OFF_W     86016
#define OFF_LIST  104448
#define OFF_WCNT  104960
#define SMEM_SP   105216

// ---------------- device scratch ----------------
__device__ int      g_lut[PB * PD3];
__device__ int      g_nbr[27 * BN];
__device__ __half   g_tmp16[(size_t)BN * PC];
__device__ __half   g_h16[(size_t)BN * PC];
__device__ __half   g_wt16[4 * 27 * PC * PC];
__device__ float    g_part[2 * STAT_BLOCKS * PC];
__device__ float    g_scale[PC];
__device__ float    g_shift[PC];
__device__ unsigned g_tick;

// ---------------- helpers ----------------
__device__ __forceinline__ uint32_t smem_u32(const void* p) {
    uint32_t a;
    asm("{ .reg .u64 t; cvta.to.shared.u64 t, %1; cvt.u32.u64 %0, t; }" : "=r"(a) : "l"(p));
    return a;
}

__device__ __forceinline__ void finalize_in_block(
    float* red, int t, const float* __restrict__ gamma, const float* __restrict__ beta) {
    int c = t & 63, seg = t >> 6;
    float S = 0.f, Q = 0.f;
    for (int b = seg * 256; b < (seg + 1) * 256; b++) {
        S += g_part[b * 64 + c];
        Q += g_part[STAT_BLOCKS * 64 + b * 64 + c];
    }
    red[t] = S; red[256 + t] = Q;
    __syncthreads();
    if (t < 64) {
        float s = red[t] + red[t + 64] + red[t + 128] + red[t + 192];
        float q = red[256 + t] + red[256 + t + 64] + red[256 + t + 128] + red[256 + t + 192];
        const float inv = 1.0f / (float)BN;
        float mu = s * inv;
        float var = q * inv - mu * mu;
        float rstd = rsqrtf(var + EPSV);
        float sc = rstd * gamma[t];
        g_scale[t] = sc;
        g_shift[t] = beta[t] - mu * sc;
    }
}

// ---------------- launch 0: stats on feats (f32) WITH fused finalize ----------------
__global__ void stats0_fused_kernel(const float* __restrict__ x,
                                    const float* __restrict__ gamma,
                                    const float* __restrict__ beta) {
    __shared__ float red[2048];
    __shared__ int is_last;
    int t = threadIdx.x;
    size_t gid = (size_t)blockIdx.x * 256 + t;
    const float4* x4 = (const float4*)x;
    float4 s = make_float4(0, 0, 0, 0), q = make_float4(0, 0, 0, 0);
    for (size_t i = gid; i < (size_t)TOTE / 4; i += (size_t)256 * STAT_BLOCKS) {
        float4 v = x4[i];
        s.x += v.x; s.y += v.y; s.z += v.z; s.w += v.w;
        q.x += v.x * v.x; q.y += v.y * v.y; q.z += v.z * v.z; q.w += v.w * v.w;
    }
    red[t * 4 + 0] = s.x; red[t * 4 + 1] = s.y; red[t * 4 + 2] = s.z; red[t * 4 + 3] = s.w;
    red[1024 + t * 4 + 0] = q.x; red[1024 + t * 4 + 1] = q.y;
    red[1024 + t * 4 + 2] = q.z; red[1024 + t * 4 + 3] = q.w;
    __syncthreads();
    if (t < 64) {
        int comp = t & 3, grp = t >> 2;
        float S = 0.f, Q = 0.f;
#pragma unroll
        for (int m = 0; m < 16; m++) {
            int o = grp + m * 16;
            S += red[o * 4 + comp];
            Q += red[1024 + o * 4 + comp];
        }
        g_part[blockIdx.x * 64 + t] = S;
        g_part[STAT_BLOCKS * 64 + blockIdx.x * 64 + t] = Q;
    }
    __syncthreads();
    if (t == 0) {
        __threadfence();
        unsigned old = atomicAdd(&g_tick, 1u);
        is_last = (old == STAT_BLOCKS - 1);
        if (is_last) g_tick = 0;
    }
    __syncthreads();
    if (is_last) finalize_in_block(red, t, gamma, beta);
}

// ---------------- launch 1: bnrelu(feats) + scatter_lut + wprep ----------------
__global__ void bnrelu0_fused_kernel(const float* __restrict__ x, __half* __restrict__ y,
                                     const int* __restrict__ pos,
                                     const float* __restrict__ Ws) {
    int i = blockIdx.x * blockDim.x + threadIdx.x;
    if (i < BN) {
        int b = i / PN;
        int code = (pos[3 * i] * PD + pos[3 * i + 1]) * PD + pos[3 * i + 2];
        g_lut[b * PD3 + code] = i - b * PN;
    }
    if (i < 4 * 27 * 4096) {
        int mat = i >> 12;
        int co  = (i >> 6) & 63;
        int ci  = i & 63;
        g_wt16[i] = __float2half_rn(Ws[mat * 4096 + ci * 64 + co]);
    }
    if (i >= TOTE / 8) return;
    const float4* x4 = (const float4*)x;
    float4 v0 = x4[2 * i], v1 = x4[2 * i + 1];
    int c8 = i & 7;
    float4 sc0 = ((const float4*)g_scale)[2 * c8], sc1 = ((const float4*)g_scale)[2 * c8 + 1];
    float4 sh0 = ((const float4*)g_shift)[2 * c8], sh1 = ((const float4*)g_shift)[2 * c8 + 1];
    __half2 h[4];
    h[0] = __floats2half2_rn(fmaxf(fmaf(v0.x, sc0.x, sh0.x), 0.f),
                             fmaxf(fmaf(v0.y, sc0.y, sh0.y), 0.f));
    h[1] = __floats2half2_rn(fmaxf(fmaf(v0.z, sc0.z, sh0.z), 0.f),
                             fmaxf(fmaf(v0.w, sc0.w, sh0.w), 0.f));
    h[2] = __floats2half2_rn(fmaxf(fmaf(v1.x, sc1.x, sh1.x), 0.f),
                             fmaxf(fmaf(v1.y, sc1.y, sh1.y), 0.f));
    h[3] = __floats2half2_rn(fmaxf(fmaf(v1.z, sc1.z, sh1.z), 0.f),
                             fmaxf(fmaf(v1.w, sc1.w, sh1.w), 0.f));
    ((uint4*)y)[i] = *(uint4*)h;
}

// ---------------- launch 2: neighbor table ----------------
__global__ void build_nbr_kernel(const int* __restrict__ pos) {
    int i = blockIdx.x * blockDim.x + threadIdx.x;
    if (i >= BN) return;
    int b = i / PN;
    int px = pos[3 * i], py = pos[3 * i + 1], pz = pos[3 * i + 2];
    const int* lutb = g_lut + b * PD3;
#pragma unroll
    for (int k = 0; k < 27; k++) {
        int nx = px + k / 9 - 1, ny = py + (k / 3) % 3 - 1, nz = pz + k % 3 - 1;
        int nidx = -1;
        if (((unsigned)nx < PD) & ((unsigned)ny < PD) & ((unsigned)nz < PD))
            nidx = lutb[(nx * PD + ny) * PD + nz];
        g_nbr[k * BN + i] = nidx;
    }
}

// ---------------- BN kernels ----------------
__global__ void stats_kernel(const float* __restrict__ x) {
    __shared__ float red[2048];
    int t = threadIdx.x;
    size_t gid = (size_t)blockIdx.x * 256 + t;
    const float4* x4 = (const float4*)x;
    float4 s = make_float4(0, 0, 0, 0), q = make_float4(0, 0, 0, 0);
    for (size_t i = gid; i < (size_t)TOTE / 4; i += (size_t)256 * STAT_BLOCKS) {
        float4 v = x4[i];
        s.x += v.x; s.y += v.y; s.z += v.z; s.w += v.w;
        q.x += v.x * v.x; q.y += v.y * v.y; q.z += v.z * v.z; q.w += v.w * v.w;
    }
    red[t * 4 + 0] = s.x; red[t * 4 + 1] = s.y; red[t * 4 + 2] = s.z; red[t * 4 + 3] = s.w;
    red[1024 + t * 4 + 0] = q.x; red[1024 + t * 4 + 1] = q.y;
    red[1024 + t * 4 + 2] = q.z; red[1024 + t * 4 + 3] = q.w;
    __syncthreads();
    if (t < 64) {
        int comp = t & 3, grp = t >> 2;
        float S = 0.f, Q = 0.f;
#pragma unroll
        for (int m = 0; m < 16; m++) {
            int o = grp + m * 16;
            S += red[o * 4 + comp];
            Q += red[1024 + o * 4 + comp];
        }
        g_part[blockIdx.x * 64 + t] = S;
        g_part[STAT_BLOCKS * 64 + blockIdx.x * 64 + t] = Q;
    }
}

__global__ void stats16_kernel(const __half* __restrict__ x) {
    __shared__ float red[4096];
    int t = threadIdx.x;
    size_t gid = (size_t)blockIdx.x * 256 + t;
    const uint4* x8 = (const uint4*)x;
    float s[8] = {0, 0, 0, 0, 0, 0, 0, 0}, q[8] = {0, 0, 0, 0, 0, 0, 0, 0};
    for (size_t i = gid; i < (size_t)TOTE / 8; i += (size_t)256 * STAT_BLOCKS) {
        uint4 u = x8[i];
        const __half2* h2 = (const __half2*)&u;
#pragma unroll
        for (int j = 0; j < 4; j++) {
            float2 f = __half22float2(h2[j]);
            s[2 * j] += f.x;     q[2 * j] += f.x * f.x;
            s[2 * j + 1] += f.y; q[2 * j + 1] += f.y * f.y;
        }
    }
#pragma unroll
    for (int j = 0; j < 8; j++) { red[t * 8 + j] = s[j]; red[2048 + t * 8 + j] = q[j]; }
    __syncthreads();
    if (t < 64) {
        int grp = t >> 3;
        int sub = t & 7;
        float S = 0.f, Q = 0.f;
#pragma unroll
        for (int m = 0; m < 32; m++) {
            int tt = grp + m * 8;
            S += red[tt * 8 + sub];
            Q += red[2048 + tt * 8 + sub];
        }
        g_part[blockIdx.x * 64 + t] = S;
        g_part[STAT_BLOCKS * 64 + blockIdx.x * 64 + t] = Q;
    }
}

__global__ void finalize_stats_kernel(const float* __restrict__ gamma,
                                      const float* __restrict__ beta) {
    __shared__ float r[512];
    int t = threadIdx.x;
    finalize_in_block(r, t, gamma, beta);
}

__global__ void bnrelu_kernel(const float* __restrict__ x, __half* __restrict__ y) {
    int i = blockIdx.x * blockDim.x + threadIdx.x;
    if (i >= TOTE / 8) return;
    const float4* x4 = (const float4*)x;
    float4 v0 = x4[2 * i], v1 = x4[2 * i + 1];
    int c8 = i & 7;
    float4 sc0 = ((const float4*)g_scale)[2 * c8], sc1 = ((const float4*)g_scale)[2 * c8 + 1];
    float4 sh0 = ((const float4*)g_shift)[2 * c8], sh1 = ((const float4*)g_shift)[2 * c8 + 1];
    __half2 h[4];
    h[0] = __floats2half2_rn(fmaxf(fmaf(v0.x, sc0.x, sh0.x), 0.f),
                             fmaxf(fmaf(v0.y, sc0.y, sh0.y), 0.f));
    h[1] = __floats2half2_rn(fmaxf(fmaf(v0.z, sc0.z, sh0.z), 0.f),
                             fmaxf(fmaf(v0.w, sc0.w, sh0.w), 0.f));
    h[2] = __floats2half2_rn(fmaxf(fmaf(v1.x, sc1.x, sh1.x), 0.f),
                             fmaxf(fmaf(v1.y, sc1.y, sh1.y), 0.f));
    h[3] = __floats2half2_rn(fmaxf(fmaf(v1.z, sc1.z, sh1.z), 0.f),
                             fmaxf(fmaf(v1.w, sc1.w, sh1.w), 0.f));
    ((uint4*)y)[i] = *(uint4*)h;
}

__global__ void bnrelu16_kernel(const __half* __restrict__ x, __half* __restrict__ y) {
    int i = blockIdx.x * blockDim.x + threadIdx.x;
    if (i >= TOTE / 8) return;
    uint4 u = ((const uint4*)x)[i];
    const __half2* h2 = (const __half2*)&u;
    int c8 = i & 7;
    float4 sc0 = ((const float4*)g_scale)[2 * c8], sc1 = ((const float4*)g_scale)[2 * c8 + 1];
    float4 sh0 = ((const float4*)g_shift)[2 * c8], sh1 = ((const float4*)g_shift)[2 * c8 + 1];
    float2 f0 = __half22float2(h2[0]), f1 = __half22float2(h2[1]);
    float2 f2 = __half22float2(h2[2]), f3 = __half22float2(h2[3]);
    __half2 h[4];
    h[0] = __floats2half2_rn(fmaxf(fmaf(f0.x, sc0.x, sh0.x), 0.f),
                             fmaxf(fmaf(f0.y, sc0.y, sh0.y), 0.f));
    h[1] = __floats2half2_rn(fmaxf(fmaf(f1.x, sc0.z, sh0.z), 0.f),
                             fmaxf(fmaf(f1.y, sc0.w, sh0.w), 0.f));
    h[2] = __floats2half2_rn(fmaxf(fmaf(f2.x, sc1.x, sh1.x), 0.f),
                             fmaxf(fmaf(f2.y, sc1.y, sh1.y), 0.f));
    h[3] = __floats2half2_rn(fmaxf(fmaf(f3.x, sc1.z, sh1.z), 0.f),
                             fmaxf(fmaf(f3.y, sc1.w, sh1.w), 0.f));
    ((uint4*)y)[i] = *(uint4*)h;
}

// ---------------- sparse conv: R16 remap + center-tap-first specialization ----------------
// Center tap (k=13, neighbor==self) processed first as 4 dense identity chunks with
// OVERWRITE stores -> no acc zero-init, no center RMW reads, no ballot for it.
// Remaining 26 taps: unmodified R16 loop over ktap = idx + (idx>=13).
template <typename OutT>
__global__ __launch_bounds__(256, 2) void conv_sp_kernel(
    const __half* __restrict__ h, const __half* __restrict__ wt,
    OutT* __restrict__ out, const float* __restrict__ addsrc) {
    extern __shared__ char smem[];
    const uint32_t sbase = smem_u32(smem);
    const int tid  = threadIdx.x;
    const int lane = tid & 31;
    const int wid  = tid >> 5;
    const int g    = lane >> 2;
    const int tig  = lane & 3;
    const int nh   = wid & 3;      // n16 slice
    const int mh   = wid >> 2;     // row half
    const int b    = blockIdx.y;
    const int pt0  = blockIdx.x * TILE_M;
    const __half* hb = h + (size_t)b * PN * PC;

    float* accf  = (float*)smem;
    int*   slist = (int*)(smem + OFF_LIST);
    int*   swcnt = (int*)(smem + OFF_WCNT);

    const int  gp   = pt0 + tid;
    const bool inr  = gp < PN;
    const size_t gidx = (size_t)b * PN + gp;

    int pref = inr ? g_nbr[gidx] : -1;   // prefetch tap 0 (first list tap)
    int nidx = -1, rank = 0, cnt = 0;

    // list-tap iteration over idx 0..25, ktap = idx + (idx>=13)
    auto new_tap = [&](int idx) {
        nidx = pref;
        int nidx2 = idx + 1;
        int knext = nidx2 + (nidx2 >= 13);
        pref = (nidx2 < 26 && inr) ? g_nbr[(size_t)knext * BN + gidx] : -1;
        unsigned msk = __ballot_sync(0xffffffffu, nidx >= 0);
        if (lane == 0) swcnt[wid] = __popc(msk);
        __syncthreads();
        int base = 0, tot = 0;
#pragma unroll
        for (int j = 0; j < 8; j++) {
            int c = swcnt[j];
            base += (j < wid) ? c : 0;
            tot += c;
        }
        rank = base + __popc(msk & ((1u << lane) - 1u));
        cnt = tot;
        __syncthreads();
    };

    auto issue_w = [&](int k, int ws) {
        const char* src = (const char*)(wt + (size_t)k * 4096);
#pragma unroll
        for (int j = 0; j < 2; j++) {
            int c = tid + j * 256;
            int row = c >> 3, off = (c & 7) * 16;
            uint32_t dst = sbase + OFF_W + ws * 9216 + row * 144 + off;
            asm volatile("cp.async.ca.shared.global [%0],[%1],16;"
                         :: "r"(dst), "l"(src + row * 128 + off));
        }
    };

    auto fill_list = [&](int lo, int st) {
        if (nidx >= 0 && rank >= lo && rank < lo + 64)
            slist[st * 64 + (rank - lo)] = (nidx << 8) | tid;
    };

    auto issue_a = [&](int Rc, int st) {
        int row = tid >> 2, q = tid & 3;
        if (row < Rc) {
            int e = slist[st * 64 + row];
            const char* src = (const char*)(hb + ((size_t)(e >> 8)) * PC) + q * 32;
            uint32_t dst = sbase + OFF_A + st * 9216 + row * 144 + q * 32;
            asm volatile("cp.async.ca.shared.global [%0],[%1],16;" :: "r"(dst), "l"(src));
            asm volatile("cp.async.ca.shared.global [%0],[%1],16;" :: "r"(dst + 16), "l"(src + 16));
        }
        asm volatile("cp.async.commit_group;" ::: "memory");
    };

    // center tap: dense identity gather of rows [c4*64, c4*64+64)
    auto issue_a_center = [&](int c4, int st) {
        int row = tid >> 2, q = tid & 3;
        int p = pt0 + c4 * 64 + row;
        int pp = (p < PN) ? p : 0;   // clamp; garbage rows never consumed
        const char* src = (const char*)(hb + (size_t)pp * PC) + q * 32;
        uint32_t dst = sbase + OFF_A + st * 9216 + row * 144 + q * 32;
        asm volatile("cp.async.ca.shared.global [%0],[%1],16;" :: "r"(dst), "l"(src));
        asm volatile("cp.async.ca.shared.global [%0],[%1],16;" :: "r"(dst + 16), "l"(src + 16));
        asm volatile("cp.async.commit_group;" ::: "memory");
    };

    uint32_t bw[4][4];
    auto load_b = [&](int ws) {
        const uint32_t brow = (uint32_t)(nh * 16 + ((lane >> 4) & 1) * 8 + (lane & 7)) * 144 +
                              ((lane >> 3) & 1) * 16;
#pragma unroll
        for (int j = 0; j < 4; j++) {
            uint32_t ad = sbase + OFF_W + ws * 9216 + brow + j * 32;
            asm volatile("ldmatrix.sync.aligned.m8n8.x4.shared.b16 {%0,%1,%2,%3},[%4];"
                         : "=r"(bw[j][0]), "=r"(bw[j][1]), "=r"(bw[j][2]), "=r"(bw[j][3])
                         : "r"(ad));
        }
    };

    // MMA core: computes c0/c1 for tile mt from A stage st
    auto mma_mt = [&](int st, int mt, float* c0, float* c1) {
        uint32_t ab = sbase + OFF_A + st * 9216 + (uint32_t)(lane & 15) * 144 +
                      (lane >> 4) * 16;
        uint32_t a[4];
#pragma unroll
        for (int j = 0; j < 4; j++) {
            asm volatile("ldmatrix.sync.aligned.m8n8.x4.shared.b16 {%0,%1,%2,%3},[%4];"
                         : "=r"(a[0]), "=r"(a[1]), "=r"(a[2]), "=r"(a[3])
                         : "r"(ab + mt * 2304 + j * 32));
            asm volatile(
                "mma.sync.aligned.m16n8k16.row.col.f32.f16.f16.f32 "
                "{%0,%1,%2,%3},{%4,%5,%6,%7},{%8,%9},{%0,%1,%2,%3};"
                : "+f"(c0[0]), "+f"(c0[1]), "+f"(c0[2]), "+f"(c0[3])
                : "r"(a[0]), "r"(a[1]), "r"(a[2]), "r"(a[3]),
                  "r"(bw[j][0]), "r"(bw[j][1]));
            asm volatile(
                "mma.sync.aligned.m16n8k16.row.col.f32.f16.f16.f32 "
                "{%0,%1,%2,%3},{%4,%5,%6,%7},{%8,%9},{%0,%1,%2,%3};"
                : "+f"(c1[0]), "+f"(c1[1]), "+f"(c1[2]), "+f"(c1[3])
                : "r"(a[0]), "r"(a[1]), "r"(a[2]), "r"(a[3]),
                  "r"(bw[j][2]), "r"(bw[j][3]));
        }
    };

    // list-tap chunk: RMW scatter-add via slist
    auto do_chunk = [&](int st, int Rc) {
        const int colb = nh * 16 + 2 * tig;
#pragma unroll
        for (int mtt = 0; mtt < 2; mtt++) {
            int mt = mh * 2 + mtt;
            if (mt * 16 >= Rc) break;
            float c0[4] = {0.f, 0.f, 0.f, 0.f};
            float c1[4] = {0.f, 0.f, 0.f, 0.f};
            mma_mt(st, mt, c0, c1);
            int r0 = mt * 16 + g;
            if (r0 < Rc) {
                int t = slist[st * 64 + r0] & 255;
                float* base = accf + (size_t)t * ACC_STRIDE + colb;
                float2* p0 = (float2*)base;
                float2 v0 = *p0; v0.x += c0[0]; v0.y += c0[1]; *p0 = v0;
                float2* p1 = (float2*)(base + 8);
                float2 v1 = *p1; v1.x += c1[0]; v1.y += c1[1]; *p1 = v1;
            }
            if (r0 + 8 < Rc) {
                int t = slist[st * 64 + r0 + 8] & 255;
                float* base = accf + (size_t)t * ACC_STRIDE + colb;
                float2* p0 = (float2*)base;
                float2 v0 = *p0; v0.x += c0[2]; v0.y += c0[3]; *p0 = v0;
                float2* p1 = (float2*)(base + 8);
                float2 v1 = *p1; v1.x += c1[2]; v1.y += c1[3]; *p1 = v1;
            }
        }
    };

    // center chunk: identity rows, OVERWRITE (initializes acc)
    auto do_center = [&](int st, int c4) {
        const int colb = nh * 16 + 2 * tig;
#pragma unroll
        for (int mtt = 0; mtt < 2; mtt++) {
            int mt = mh * 2 + mtt;
            float c0[4] = {0.f, 0.f, 0.f, 0.f};
            float c1[4] = {0.f, 0.f, 0.f, 0.f};
            mma_mt(st, mt, c0, c1);
            int r0 = c4 * 64 + mt * 16 + g;
            {
                float* base = accf + (size_t)r0 * ACC_STRIDE + colb;
                *(float2*)base = make_float2(c0[0], c0[1]);
                *(float2*)(base + 8) = make_float2(c1[0], c1[1]);
            }
            {
                float* base = accf + (size_t)(r0 + 8) * ACC_STRIDE + colb;
                *(float2*)base = make_float2(c0[2], c0[3]);
                *(float2*)(base + 8) = make_float2(c1[2], c1[3]);
            }
        }
    };

    // ---- phase 1: center tap (k=13), 4 dense chunks, overwrite ----
    issue_w(13, 0);
    issue_a_center(0, 0);
    __syncthreads();   // ensure W issue visible ordering for all warps (cheap)
    for (int c4 = 0; c4 < 4; c4++) {
        if (c4 + 1 < 4) {
            issue_a_center(c4 + 1, (c4 + 1) & 1);
            asm volatile("cp.async.wait_group 1;" ::: "memory");
        } else {
            asm volatile("cp.async.wait_group 0;" ::: "memory");
        }
        __syncthreads();
        if (c4 == 0) load_b(0);
        do_center(c4 & 1, c4);
        __syncthreads();
    }

    // ---- phase 2: remaining 26 taps (R16 loop) ----
    int idx = 0;
    new_tap(0);
    while (cnt == 0 && idx < 25) { idx++; new_tap(idx); }
    if (cnt > 0) {
        issue_w(idx + (idx >= 13), 1);
        fill_list(0, 0);
        __syncthreads();
        int firstRc = (cnt < 64) ? cnt : 64;
        issue_a(firstRc, 0);

        int curidx = idx, curlo = 0, curst = 0, curWst = 1, curRc = firstRc;
        bool curNew = true;
        int tapcnt = cnt;

        while (true) {
            int nRc = 0, nst = curst ^ 1, nWst = curWst, nidx2 = curidx, nlo = 0;
            bool nNew = false;
            if (curlo + 64 < tapcnt) {
                nidx2 = curidx; nlo = curlo + 64;
                nRc = tapcnt - nlo; if (nRc > 64) nRc = 64;
                fill_list(nlo, nst);
                __syncthreads();
                issue_a(nRc, nst);
            } else {
                int i2 = curidx + 1;
                while (i2 < 26) { new_tap(i2); if (cnt > 0) break; i2++; }
                if (i2 < 26) {
                    nidx2 = i2; nlo = 0; nNew = true; nWst = curWst ^ 1;
                    nRc = (cnt < 64) ? cnt : 64;
                    issue_w(i2 + (i2 >= 13), nWst);
                    fill_list(0, nst);
                    __syncthreads();
                    issue_a(nRc, nst);
                }
            }
            if (nRc > 0) asm volatile("cp.async.wait_group 1;" ::: "memory");
            else         asm volatile("cp.async.wait_group 0;" ::: "memory");
            __syncthreads();
            if (curNew) load_b(curWst);
            do_chunk(curst, curRc);
            __syncthreads();
            if (nRc == 0) break;
            curidx = nidx2; curlo = nlo; curst = nst; curWst = nWst;
            curNew = nNew; curRc = nRc;
            if (nNew) tapcnt = cnt;
        }
    }

    // ---- epilogue ----
    const bool doadd = (addsrc != nullptr);
    for (int r32 = 0; r32 < 32; r32++) {
        int row = wid * 32 + r32;
        int p = pt0 + row;
        if (p < PN) {
            float2 v = *(float2*)(accf + (size_t)row * ACC_STRIDE + lane * 2);
            size_t o = ((size_t)b * PN + p) * PC + lane * 2;
            if constexpr (sizeof(OutT) == 4) {
                if (doadd) {
                    float2 a2 = *(const float2*)(addsrc + o);
                    v.x += a2.x; v.y += a2.y;
                }
                *(float2*)((float*)out + o) = v;
            } else {
                *(__half2*)((__half*)out + o) = __floats2half2_rn(v.x, v.y);
            }
        }
    }
}

// ---------------- host orchestration ----------------
extern "C" void kernel_launch(void* const* d_in, const int* in_sizes, int n_in,
                              void* d_out, int out_size) {
    const float* feats  = (const float*)d_in[0];
    const float* Ws     = (const float*)d_in[1];
    const float* gammas = (const float*)d_in[2];
    const float* betas  = (const float*)d_in[3];
    const int*   pos    = (const int*)d_in[4];
    float* x = (float*)d_out;

    __half *h16, *wt16, *tmp16;
    int* lut;
    cudaGetSymbolAddress((void**)&h16, g_h16);
    cudaGetSymbolAddress((void**)&wt16, g_wt16);
    cudaGetSymbolAddress((void**)&tmp16, g_tmp16);
    cudaGetSymbolAddress((void**)&lut, g_lut);

    cudaFuncSetAttribute(conv_sp_kernel<float>,
                         cudaFuncAttributeMaxDynamicSharedMemorySize, SMEM_SP);
    cudaFuncSetAttribute(conv_sp_kernel<__half>,
                         cudaFuncAttributeMaxDynamicSharedMemorySize, SMEM_SP);

    cudaMemsetAsync(lut, 0xFF, sizeof(int) * PB * PD3, 0);

    dim3 cgrid(NTILES, PB);
    const int bnb = (TOTE / 8 + 255) / 256;

    stats0_fused_kernel<<<STAT_BLOCKS, 256>>>(feats, gammas + 0 * PC, betas + 0 * PC);
    bnrelu0_fused_kernel<<<bnb, 256>>>(feats, h16, pos, Ws);
    build_nbr_kernel<<<(BN + 255) / 256, 256>>>(pos);

    conv_sp_kernel<__half><<<cgrid, 256, SMEM_SP>>>(
        h16, wt16 + (size_t)0 * 27 * 4096, tmp16, nullptr);
    stats16_kernel<<<STAT_BLOCKS, 256>>>(tmp16);
    finalize_stats_kernel<<<1, 256>>>(gammas + 1 * PC, betas + 1 * PC);
    bnrelu16_kernel<<<bnb, 256>>>(tmp16, h16);
    conv_sp_kernel<float><<<cgrid, 256, SMEM_SP>>>(
        h16, wt16 + (size_t)1 * 27 * 4096, x, feats);

    stats_kernel<<<STAT_BLOCKS, 256>>>(x);
    finalize_stats_kernel<<<1, 256>>>(gammas + 2 * PC, betas + 2 * PC);
    bnrelu_kernel<<<bnb, 256>>>(x, h16);
    conv_sp_kernel<__half><<<cgrid, 256, SMEM_SP>>>(
        h16, wt16 + (size_t)2 * 27 * 4096, tmp16, nullptr);
    stats16_kernel<<<STAT_BLOCKS, 256>>>(tmp16);
    finalize_stats_kernel<<<1, 256>>>(gammas + 3 * PC, betas + 3 * PC);
    bnrelu16_kernel<<<bnb, 256>>>(tmp16, h16);
    conv_sp_kernel<float><<<cgrid, 256, SMEM_SP>>>(
        h16, wt16 + (size_t)3 * 27 * 4096, x, x);
}